// round 3
// baseline (speedup 1.0000x reference)
#include <cuda_runtime.h>
#include <math.h>
#include <stdint.h>

#define NN 50000
#define NE 600000
#define FIN 128
#define HID 64
#define C1 256
#define SENTD 768
#define NB 196   /* ceil(NN/256) */

// ---------------- device scratch ----------------
__device__ __align__(16) float g_h1lin[(size_t)NN * C1];   // x@W1
__device__ __align__(16) float g_out1 [(size_t)NN * C1];   // LN(elu(agg1+b1))
__device__ __align__(16) float g_h2lin[(size_t)NN * HID];  // h1n@W2
__device__ __align__(16) float g_es1[NN * 4];
__device__ __align__(16) float g_ed1[NN * 4];
__device__ float g_es2[NN], g_ed2[NN];
__device__ float g_sent[HID];
// CSR
__device__ int g_deg[NN];
__device__ int g_rowstart[NN + 1];
__device__ int g_fill[NN];
__device__ int g_csrc[NE];
__device__ int g_eorig[NE];
__device__ int g_blksum[256];
__device__ int g_blkoff[256];

// ---------------- helpers ----------------
__device__ __forceinline__ float warp_sum(float v) {
    #pragma unroll
    for (int o = 16; o; o >>= 1) v += __shfl_xor_sync(0xffffffffu, v, o);
    return v;
}
__device__ __forceinline__ float lrelu02(float v) { return v > 0.f ? v : 0.2f * v; }

__device__ __forceinline__ unsigned long long dup2(float x) {
    unsigned long long r;
    asm("mov.b64 %0, {%1, %1};" : "=l"(r) : "f"(x));
    return r;
}
__device__ __forceinline__ unsigned long long ffma2(unsigned long long a,
                                                    unsigned long long b,
                                                    unsigned long long c) {
    unsigned long long d;
    asm("fma.rn.f32x2 %0, %1, %2, %3;" : "=l"(d) : "l"(a), "l"(b), "l"(c));
    return d;
}
__device__ __forceinline__ float lo32(unsigned long long v) {
    return __uint_as_float((unsigned)(v & 0xffffffffull));
}
__device__ __forceinline__ float hi32(unsigned long long v) {
    return __uint_as_float((unsigned)(v >> 32));
}

// ================= CSR build =================
__global__ void k_zero() {
    int i = blockIdx.x * blockDim.x + threadIdx.x;
    if (i < NN) g_deg[i] = 0;
}
__global__ void k_hist(const int* __restrict__ ei) {
    int e = blockIdx.x * blockDim.x + threadIdx.x;
    if (e < NE) atomicAdd(&g_deg[ei[NE + e]], 1);
}
__global__ void k_scan1() {
    __shared__ int sh[256];
    int i = blockIdx.x * 256 + threadIdx.x;
    sh[threadIdx.x] = (i < NN) ? g_deg[i] : 0;
    __syncthreads();
    for (int o = 128; o; o >>= 1) {
        if (threadIdx.x < o) sh[threadIdx.x] += sh[threadIdx.x + o];
        __syncthreads();
    }
    if (!threadIdx.x) g_blksum[blockIdx.x] = sh[0];
}
__global__ void k_scan2() {
    __shared__ int sh[256];
    int t = threadIdx.x;
    int v = (t < NB) ? g_blksum[t] : 0;
    sh[t] = v; __syncthreads();
    for (int o = 1; o < 256; o <<= 1) {
        int x = (t >= o) ? sh[t - o] : 0;
        __syncthreads();
        sh[t] += x;
        __syncthreads();
    }
    g_blkoff[t] = sh[t] - v;
    if (t == 0) g_rowstart[NN] = NE;
}
__global__ void k_scan3() {
    __shared__ int sh[256];
    int t = threadIdx.x, i = blockIdx.x * 256 + t;
    int v = (i < NN) ? g_deg[i] : 0;
    sh[t] = v; __syncthreads();
    for (int o = 1; o < 256; o <<= 1) {
        int x = (t >= o) ? sh[t - o] : 0;
        __syncthreads();
        sh[t] += x;
        __syncthreads();
    }
    int excl = sh[t] - v + g_blkoff[blockIdx.x];
    if (i < NN) { g_rowstart[i] = excl; g_fill[i] = excl; }
}
__global__ void k_fill(const int* __restrict__ ei) {
    int e = blockIdx.x * blockDim.x + threadIdx.x;
    if (e >= NE) return;
    int s = ei[e], d = ei[NE + e];
    int p = atomicAdd(&g_fill[d], 1);
    g_csrc[p] = s;
    g_eorig[p] = e;
}

// ================= GEMM1 fused (x@W1 -> g_h1lin, + es1/ed1) =================
// BM=128 BN=128 BK=16 TM=8 TN=8, 256 threads, f32x2 packed FMA
__global__ __launch_bounds__(256) void gemm1_fused(const float* __restrict__ A,
        const float* __restrict__ B, const float* __restrict__ asrc,
        const float* __restrict__ adst) {
    __shared__ unsigned long long As2[16][128];
    __shared__ float Bs[16][128];
    const int tid = threadIdx.x;
    const int bm = blockIdx.y * 128, bn = blockIdx.x * 128;
    const int tcol = tid & 15, trow = tid >> 4;

    unsigned long long acc2[8][4];
    #pragma unroll
    for (int i = 0; i < 8; i++)
        #pragma unroll
        for (int j = 0; j < 4; j++) acc2[i][j] = 0ull;

    for (int k0 = 0; k0 < FIN; k0 += 16) {
        #pragma unroll
        for (int i = tid; i < 512; i += 256) {
            int r = i >> 2, kc = (i & 3) * 4;
            float4 v = make_float4(0.f, 0.f, 0.f, 0.f);
            if (bm + r < NN) v = *(const float4*)&A[(size_t)(bm + r) * FIN + k0 + kc];
            As2[kc + 0][r] = dup2(v.x); As2[kc + 1][r] = dup2(v.y);
            As2[kc + 2][r] = dup2(v.z); As2[kc + 3][r] = dup2(v.w);
        }
        #pragma unroll
        for (int i = tid; i < 512; i += 256) {
            int kr = i >> 5, nc = (i & 31) * 4;
            *(float4*)&Bs[kr][nc] = *(const float4*)&B[(size_t)(k0 + kr) * C1 + bn + nc];
        }
        __syncthreads();
        #pragma unroll
        for (int kk = 0; kk < 16; kk++) {
            unsigned long long a2[8], b2[4];
            #pragma unroll
            for (int i = 0; i < 8; i += 2)
                *(ulonglong2*)&a2[i] = *(const ulonglong2*)&As2[kk][trow * 8 + i];
            const unsigned long long* bp = (const unsigned long long*)&Bs[kk][tcol * 8];
            *(ulonglong2*)&b2[0] = *(const ulonglong2*)&bp[0];
            *(ulonglong2*)&b2[2] = *(const ulonglong2*)&bp[2];
            #pragma unroll
            for (int i = 0; i < 8; i++)
                #pragma unroll
                for (int j = 0; j < 4; j++) acc2[i][j] = ffma2(a2[i], b2[j], acc2[i][j]);
        }
        __syncthreads();
    }
    // unpack + store + attention epilogue
    const int headg = (bn + tcol * 8) >> 6;
    float as_[8], ad_[8];
    #pragma unroll
    for (int j = 0; j < 8; j++) {
        int col = (bn + tcol * 8 + j) & 63;
        as_[j] = asrc[headg * 64 + col];
        ad_[j] = adst[headg * 64 + col];
    }
    #pragma unroll
    for (int i = 0; i < 8; i++) {
        float f[8];
        #pragma unroll
        for (int j = 0; j < 4; j++) { f[2*j] = lo32(acc2[i][j]); f[2*j+1] = hi32(acc2[i][j]); }
        int r = bm + trow * 8 + i;
        bool ok = r < NN;
        if (ok) {
            float* cp = &g_h1lin[(size_t)r * C1 + bn + tcol * 8];
            *(float4*)cp       = make_float4(f[0], f[1], f[2], f[3]);
            *(float4*)(cp + 4) = make_float4(f[4], f[5], f[6], f[7]);
        }
        float es = 0.f, ed = 0.f;
        #pragma unroll
        for (int j = 0; j < 8; j++) { es += f[j] * as_[j]; ed += f[j] * ad_[j]; }
        es += __shfl_xor_sync(0xffffffffu, es, 1);
        es += __shfl_xor_sync(0xffffffffu, es, 2);
        es += __shfl_xor_sync(0xffffffffu, es, 4);
        ed += __shfl_xor_sync(0xffffffffu, ed, 1);
        ed += __shfl_xor_sync(0xffffffffu, ed, 2);
        ed += __shfl_xor_sync(0xffffffffu, ed, 4);
        if (ok && (tid & 7) == 0) { g_es1[r * 4 + headg] = es; g_ed1[r * 4 + headg] = ed; }
    }
}

// ================= GEMM2 fused (g_out1@W2 -> g_h2lin, + es2/ed2) =================
// BM=128 BN=64 BK=16 TM=8 TN=4, 256 threads
__global__ __launch_bounds__(256) void gemm2_fused(const float* __restrict__ B,
        const float* __restrict__ asrc, const float* __restrict__ adst) {
    __shared__ unsigned long long As2[16][128];
    __shared__ float Bs[16][64];
    const int tid = threadIdx.x;
    const int bm = blockIdx.y * 128;
    const int tcol = tid & 15, trow = tid >> 4;

    unsigned long long acc2[8][2];
    #pragma unroll
    for (int i = 0; i < 8; i++) { acc2[i][0] = 0ull; acc2[i][1] = 0ull; }

    for (int k0 = 0; k0 < C1; k0 += 16) {
        #pragma unroll
        for (int i = tid; i < 512; i += 256) {
            int r = i >> 2, kc = (i & 3) * 4;
            float4 v = make_float4(0.f, 0.f, 0.f, 0.f);
            if (bm + r < NN) v = *(const float4*)&g_out1[(size_t)(bm + r) * C1 + k0 + kc];
            As2[kc + 0][r] = dup2(v.x); As2[kc + 1][r] = dup2(v.y);
            As2[kc + 2][r] = dup2(v.z); As2[kc + 3][r] = dup2(v.w);
        }
        {
            int i = tid;
            if (i < 256) {
                int kr = i >> 4, nc = (i & 15) * 4;
                *(float4*)&Bs[kr][nc] = *(const float4*)&B[(size_t)(k0 + kr) * HID + nc];
            }
        }
        __syncthreads();
        #pragma unroll
        for (int kk = 0; kk < 16; kk++) {
            unsigned long long a2[8], b2[2];
            #pragma unroll
            for (int i = 0; i < 8; i += 2)
                *(ulonglong2*)&a2[i] = *(const ulonglong2*)&As2[kk][trow * 8 + i];
            *(ulonglong2*)&b2[0] = *(const ulonglong2*)&Bs[kk][tcol * 4];
            #pragma unroll
            for (int i = 0; i < 8; i++) {
                acc2[i][0] = ffma2(a2[i], b2[0], acc2[i][0]);
                acc2[i][1] = ffma2(a2[i], b2[1], acc2[i][1]);
            }
        }
        __syncthreads();
    }
    float as_[4], ad_[4];
    #pragma unroll
    for (int j = 0; j < 4; j++) { as_[j] = asrc[tcol * 4 + j]; ad_[j] = adst[tcol * 4 + j]; }
    #pragma unroll
    for (int i = 0; i < 8; i++) {
        float f[4] = { lo32(acc2[i][0]), hi32(acc2[i][0]), lo32(acc2[i][1]), hi32(acc2[i][1]) };
        int r = bm + trow * 8 + i;
        bool ok = r < NN;
        if (ok)
            *(float4*)&g_h2lin[(size_t)r * HID + tcol * 4] = make_float4(f[0], f[1], f[2], f[3]);
        float es = 0.f, ed = 0.f;
        #pragma unroll
        for (int j = 0; j < 4; j++) { es += f[j] * as_[j]; ed += f[j] * ad_[j]; }
        #pragma unroll
        for (int o = 1; o < 16; o <<= 1) {
            es += __shfl_xor_sync(0xffffffffu, es, o);
            ed += __shfl_xor_sync(0xffffffffu, ed, o);
        }
        if (ok && (tid & 15) == 0) { g_es2[r] = es; g_ed2[r] = ed; }
    }
}

// ================= layer-1 aggregation + bias + ELU + LN (one block per dst) =================
__global__ __launch_bounds__(256) void agg1(const float* __restrict__ b1,
        const float* __restrict__ lng, const float* __restrict__ lnb) {
    __shared__ int   ssrc[64];
    __shared__ float sex[256];
    __shared__ float sden[4];
    __shared__ float sself[4];
    __shared__ float sred[16];
    __shared__ float sstat[2];
    const int d = blockIdx.x, t = threadIdx.x;
    const int r0 = g_rowstart[d], r1 = g_rowstart[d + 1];
    const int hd = t >> 6;
    const int hh = t & 3, q = t >> 2;
    const float edd = g_ed1[d * 4 + hh];
    if (t < 4) sden[t] = 0.f;
    __syncthreads();
    float acc = 0.f;
    for (int base = r0; base < r1; base += 64) {
        int cnt = min(64, r1 - base);
        float ex = 0.f;
        if (q < cnt) {
            int s = g_csrc[base + q];
            if (hh == 0) ssrc[q] = s;
            ex = expf(lrelu02(g_es1[s * 4 + hh] + edd));
        }
        sex[t] = ex;
        float ww = ex;
        ww += __shfl_xor_sync(0xffffffffu, ww, 4);
        ww += __shfl_xor_sync(0xffffffffu, ww, 8);
        ww += __shfl_xor_sync(0xffffffffu, ww, 16);
        if ((t & 31) < 4) atomicAdd(&sden[hh], ww);
        __syncthreads();
        #pragma unroll 4
        for (int q2 = 0; q2 < cnt; q2++)
            acc += g_h1lin[(size_t)ssrc[q2] * C1 + t] * sex[q2 * 4 + hd];
        __syncthreads();
    }
    if (t < 4) {
        float ex = expf(lrelu02(g_es1[d * 4 + t] + g_ed1[d * 4 + t]));
        sself[t] = ex;
        atomicAdd(&sden[t], ex);
    }
    __syncthreads();
    float rd = 1.f / (sden[hd] + 1e-16f);
    float v = (acc + sself[hd] * g_h1lin[(size_t)d * C1 + t]) * rd + b1[t];
    v = v > 0.f ? v : expm1f(v);
    float s1 = warp_sum(v), s2 = warp_sum(v * v);
    int wi = t >> 5, l = t & 31;
    if (!l) { sred[wi] = s1; sred[8 + wi] = s2; }
    __syncthreads();
    if (t == 0) {
        float S = 0.f, Q = 0.f;
        #pragma unroll
        for (int k = 0; k < 8; k++) { S += sred[k]; Q += sred[8 + k]; }
        float mu = S * (1.f / C1);
        sstat[0] = mu;
        sstat[1] = rsqrtf(Q * (1.f / C1) - mu * mu + 1e-5f);
    }
    __syncthreads();
    g_out1[(size_t)d * C1 + t] = (v - sstat[0]) * sstat[1] * lng[t] + lnb[t];
}

// ================= layer-2 aggregation + alpha + bias + LN =================
__global__ __launch_bounds__(256) void agg2(const float* __restrict__ b2,
        const float* __restrict__ lng, const float* __restrict__ lnb,
        float* __restrict__ h2out, float* __restrict__ alpha_out) {
    __shared__ int   ssrc[256];
    __shared__ float sex[256];
    __shared__ float sden[1];
    __shared__ float sselfv[1];
    __shared__ float sacc[256];
    __shared__ float sred[4];
    __shared__ float sstat[2];
    const int d = blockIdx.x, t = threadIdx.x;
    const int r0 = g_rowstart[d], r1 = g_rowstart[d + 1];
    const float edd = g_ed2[d];
    if (t == 0) sden[0] = 0.f;
    __syncthreads();
    const int c = t & 63, sub = t >> 6;
    float acc = 0.f;
    int lastbase = r0;
    for (int base = r0; base < r1; base += 256) {
        lastbase = base;
        int cnt = min(256, r1 - base);
        float ex = 0.f;
        if (t < cnt) {
            int s = g_csrc[base + t];
            ssrc[t] = s;
            ex = expf(lrelu02(g_es2[s] + edd));
        }
        sex[t] = ex;
        float ww = warp_sum(ex);
        if ((t & 31) == 0) atomicAdd(&sden[0], ww);
        __syncthreads();
        for (int qq = sub; qq < cnt; qq += 4)
            acc += g_h2lin[(size_t)ssrc[qq] * HID + c] * sex[qq];
        __syncthreads();
    }
    if (t == 0) {
        float ex = expf(lrelu02(g_es2[d] + edd));
        sselfv[0] = ex;
        atomicAdd(&sden[0], ex);
    }
    __syncthreads();
    float rd = 1.f / (sden[0] + 1e-16f);
    if (t == 0) alpha_out[NE + d] = sselfv[0] * rd;
    for (int p = r0 + t; p < r1; p += 256) {
        float exv = (p >= lastbase) ? sex[p - lastbase]
                                    : expf(lrelu02(g_es2[g_csrc[p]] + edd));
        alpha_out[g_eorig[p]] = exv * rd;
    }
    sacc[t] = acc;
    __syncthreads();
    float v = 0.f;
    if (t < 64) {
        float tot = sacc[t] + sacc[64 + t] + sacc[128 + t] + sacc[192 + t]
                  + sselfv[0] * g_h2lin[(size_t)d * HID + t];
        v = tot * rd + b2[t];
    }
    float s1 = warp_sum(t < 64 ? v : 0.f);
    float s2 = warp_sum(t < 64 ? v * v : 0.f);
    if (t < 64 && !(t & 31)) { sred[t >> 5] = s1; sred[2 + (t >> 5)] = s2; }
    __syncthreads();
    if (t == 0) {
        float S = sred[0] + sred[1], Q = sred[2] + sred[3];
        float mu = S * (1.f / HID);
        sstat[0] = mu;
        sstat[1] = rsqrtf(Q * (1.f / HID) - mu * mu + 1e-5f);
    }
    __syncthreads();
    if (t < 64)
        h2out[(size_t)d * HID + t] = (v - sstat[0]) * sstat[1] * lng[t] + lnb[t];
}

// ================= sentence/step path =================
__global__ void sent_kernel(const float* __restrict__ semb, const int* __restrict__ stepp,
                            const float* __restrict__ fc0w, const float* __restrict__ fc0b,
                            const float* __restrict__ fc1w, const float* __restrict__ fc1b,
                            const float* __restrict__ fc2w, const float* __restrict__ fc2b,
                            const float* __restrict__ lng, const float* __restrict__ lnb) {
    __shared__ float sh[64];
    __shared__ float st[2];
    int c = threadIdx.x;
    float sval = (float)(stepp[0] + 1) * 0.01f;

    float t = fmaxf(sval * fc0w[c] + fc0b[c], 0.f);
    sh[c] = t; __syncthreads();
    if (c == 0) {
        float S = 0, Q = 0;
        for (int k = 0; k < 64; k++) { S += sh[k]; Q += sh[k] * sh[k]; }
        float mu = S / 64.f; st[0] = mu; st[1] = rsqrtf(Q / 64.f - mu * mu + 1e-5f);
    }
    __syncthreads();
    float steps_c = (t - st[0]) * st[1] * lng[c] + lnb[c];
    __syncthreads();

    float u = fc1b[c];
    for (int k = 0; k < SENTD; k++) u += semb[k] * fc1w[k * 64 + c];
    u = fmaxf(u, 0.f);
    sh[c] = u; __syncthreads();
    if (c == 0) {
        float S = 0, Q = 0;
        for (int k = 0; k < 64; k++) { S += sh[k]; Q += sh[k] * sh[k]; }
        float mu = S / 64.f; st[0] = mu; st[1] = rsqrtf(Q / 64.f - mu * mu + 1e-5f);
    }
    __syncthreads();
    float sc = (u - st[0]) * st[1] * lng[c] + lnb[c] + steps_c;
    __syncthreads();
    sh[c] = sc; __syncthreads();

    float v = fc2b[c];
    for (int k = 0; k < 64; k++) v += sh[k] * fc2w[k * 64 + c];
    v = fmaxf(v, 0.f);
    __syncthreads();
    sh[c] = v; __syncthreads();
    if (c == 0) {
        float S = 0, Q = 0;
        for (int k = 0; k < 64; k++) { S += sh[k]; Q += sh[k] * sh[k]; }
        float mu = S / 64.f; st[0] = mu; st[1] = rsqrtf(Q / 64.f - mu * mu + 1e-5f);
    }
    __syncthreads();
    g_sent[c] = (v - st[0]) * st[1] * lng[c] + lnb[c];
}

// ================= dueling head =================
__global__ void head_kernel(const float* __restrict__ h2base, const int* __restrict__ activep,
                            const float* __restrict__ fc3w, const float* __restrict__ fc3b,
                            const float* __restrict__ valw, const float* __restrict__ valb,
                            const float* __restrict__ advw, const float* __restrict__ advb,
                            const float* __restrict__ lnfg, const float* __restrict__ lnfb,
                            const float* __restrict__ lnhg, const float* __restrict__ lnhb,
                            float* __restrict__ outlogits) {
    __shared__ float sh[128];
    __shared__ float sh2[64];
    __shared__ float st[3];
    int c = threadIdx.x;
    int act = activep[0];
    float a = (c < 64) ? h2base[(size_t)act * 64 + c] : g_sent[c - 64];
    sh[c] = a; __syncthreads();
    if (c == 0) {
        float S = 0, Q = 0;
        for (int k = 0; k < 128; k++) { S += sh[k]; Q += sh[k] * sh[k]; }
        float mu = S / 128.f; st[0] = mu; st[1] = rsqrtf(Q / 128.f - mu * mu + 1e-5f);
    }
    __syncthreads();
    float anf = (a - st[0]) * st[1] * lnfg[c] + lnfb[c];
    __syncthreads();
    sh[c] = anf; __syncthreads();

    float t = 0.f;
    if (c < 64) {
        t = fc3b[c];
        for (int k = 0; k < 128; k++) t += sh[k] * fc3w[k * 64 + c];
        t = fmaxf(t, 0.f);
        sh2[c] = t;
    }
    __syncthreads();
    if (c == 0) {
        float S = 0, Q = 0;
        for (int k = 0; k < 64; k++) { S += sh2[k]; Q += sh2[k] * sh2[k]; }
        float mu = S / 64.f; st[0] = mu; st[1] = rsqrtf(Q / 64.f - mu * mu + 1e-5f);
    }
    __syncthreads();
    if (c < 64) sh2[c] = (t - st[0]) * st[1] * lnhg[c] + lnhb[c];
    __syncthreads();
    if (c == 0) {
        float v = valb[0];
        for (int k = 0; k < 64; k++) v += sh2[k] * valw[k];
        st[2] = v;
    }
    __syncthreads();
    float advv = 0.f;
    if (c < 32) {
        advv = advb[c];
        for (int k = 0; k < 64; k++) advv += sh2[k] * advw[k * 32 + c];
        sh[c] = advv;
    }
    __syncthreads();
    if (c == 0) {
        float m = 0;
        for (int k = 0; k < 32; k++) m += sh[k];
        st[0] = m / 32.f;
    }
    __syncthreads();
    if (c < 32) outlogits[c] = tanhf(st[2] + advv - st[0]);
}

// ================= launch =================
extern "C" void kernel_launch(void* const* d_in, const int* in_sizes, int n_in,
                              void* d_out, int out_size) {
    const float* x      = (const float*)d_in[0];
    const int*   ei     = (const int*)d_in[1];
    const float* semb   = (const float*)d_in[2];
    const int*   active = (const int*)d_in[3];
    const int*   step   = (const int*)d_in[4];
    const float* W1     = (const float*)d_in[5];
    const float* asrc1  = (const float*)d_in[6];
    const float* adst1  = (const float*)d_in[7];
    const float* b1     = (const float*)d_in[8];
    const float* W2     = (const float*)d_in[9];
    const float* asrc2  = (const float*)d_in[10];
    const float* adst2  = (const float*)d_in[11];
    const float* b2     = (const float*)d_in[12];
    const float* fc0w   = (const float*)d_in[13];
    const float* fc0b   = (const float*)d_in[14];
    const float* fc1w   = (const float*)d_in[15];
    const float* fc1b   = (const float*)d_in[16];
    const float* fc2w   = (const float*)d_in[17];
    const float* fc2b   = (const float*)d_in[18];
    const float* fc3w   = (const float*)d_in[19];
    const float* fc3b   = (const float*)d_in[20];
    const float* valw   = (const float*)d_in[21];
    const float* valb   = (const float*)d_in[22];
    const float* advw   = (const float*)d_in[23];
    const float* advb   = (const float*)d_in[24];
    const float* lnhg   = (const float*)d_in[25];
    const float* lnhb   = (const float*)d_in[26];
    const float* lnfg   = (const float*)d_in[27];
    const float* lnfb   = (const float*)d_in[28];
    const float* lnag   = (const float*)d_in[29];
    const float* lnab   = (const float*)d_in[30];
    float* out = (float*)d_out;

    float* h2out     = out + 32;
    float* alpha_out = out + 32 + (size_t)NN * HID;

    // CSR build (independent of GEMM)
    k_zero<<<NB, 256>>>();
    sent_kernel<<<1, 64>>>(semb, step, fc0w, fc0b, fc1w, fc1b, fc2w, fc2b, lnhg, lnhb);
    k_hist<<<(NE + 255) / 256, 256>>>(ei);
    k_scan1<<<NB, 256>>>();
    k_scan2<<<1, 256>>>();
    k_scan3<<<NB, 256>>>();
    k_fill<<<(NE + 255) / 256, 256>>>(ei);

    // layer 1
    gemm1_fused<<<dim3(2, (NN + 127) / 128), 256>>>(x, W1, asrc1, adst1);
    agg1<<<NN, 256>>>(b1, lnag, lnab);

    // layer 2
    gemm2_fused<<<dim3(1, (NN + 127) / 128), 256>>>(W2, asrc2, adst2);
    agg2<<<NN, 256>>>(b2, lnhg, lnhb, h2out, alpha_out);

    head_kernel<<<1, 128>>>(h2out, active, fc3w, fc3b, valw, valb, advw, advb,
                            lnfg, lnfb, lnhg, lnhb, out);
}

// round 4
// speedup vs baseline: 1.0930x; 1.0930x over previous
#include <cuda_runtime.h>
#include <math.h>
#include <stdint.h>

#define NN 50000
#define NE 600000
#define FIN 128
#define HID 64
#define C1 256
#define SENTD 768
#define NB 196   /* ceil(NN/256) */

// ---------------- device scratch ----------------
__device__ __align__(16) float g_h1lin[(size_t)NN * C1];   // x@W1
__device__ __align__(16) float g_out1 [(size_t)NN * C1];   // LN(elu(agg1+b1))
__device__ __align__(16) float g_h2lin[(size_t)NN * HID];  // h1n@W2
__device__ __align__(16) float g_es1[NN * 4];
__device__ __align__(16) float g_ed1[NN * 4];
__device__ float g_es2[NN], g_ed2[NN];
__device__ float g_sent[HID];
// CSR
__device__ int g_deg[NN];
__device__ int g_rowstart[NN + 1];
__device__ int g_fill[NN];
__device__ int g_csrc[NE];
__device__ int g_eorig[NE];
__device__ int g_blksum[256];
__device__ int g_blkoff[256];

// ---------------- helpers ----------------
__device__ __forceinline__ float warp_sum(float v) {
    #pragma unroll
    for (int o = 16; o; o >>= 1) v += __shfl_xor_sync(0xffffffffu, v, o);
    return v;
}
__device__ __forceinline__ float lrelu02(float v) { return v > 0.f ? v : 0.2f * v; }

// ================= CSR build =================
__global__ void k_zero() {
    int i = blockIdx.x * blockDim.x + threadIdx.x;
    if (i < NN) g_deg[i] = 0;
}
__global__ void k_hist(const int* __restrict__ ei) {
    int e = blockIdx.x * blockDim.x + threadIdx.x;
    if (e < NE) atomicAdd(&g_deg[ei[NE + e]], 1);
}
__global__ void k_scan1() {
    __shared__ int sh[256];
    int i = blockIdx.x * 256 + threadIdx.x;
    sh[threadIdx.x] = (i < NN) ? g_deg[i] : 0;
    __syncthreads();
    for (int o = 128; o; o >>= 1) {
        if (threadIdx.x < o) sh[threadIdx.x] += sh[threadIdx.x + o];
        __syncthreads();
    }
    if (!threadIdx.x) g_blksum[blockIdx.x] = sh[0];
}
__global__ void k_scan2() {
    __shared__ int sh[256];
    int t = threadIdx.x;
    int v = (t < NB) ? g_blksum[t] : 0;
    sh[t] = v; __syncthreads();
    for (int o = 1; o < 256; o <<= 1) {
        int x = (t >= o) ? sh[t - o] : 0;
        __syncthreads();
        sh[t] += x;
        __syncthreads();
    }
    g_blkoff[t] = sh[t] - v;
    if (t == 0) g_rowstart[NN] = NE;
}
__global__ void k_scan3() {
    __shared__ int sh[256];
    int t = threadIdx.x, i = blockIdx.x * 256 + t;
    int v = (i < NN) ? g_deg[i] : 0;
    sh[t] = v; __syncthreads();
    for (int o = 1; o < 256; o <<= 1) {
        int x = (t >= o) ? sh[t - o] : 0;
        __syncthreads();
        sh[t] += x;
        __syncthreads();
    }
    int excl = sh[t] - v + g_blkoff[blockIdx.x];
    if (i < NN) { g_rowstart[i] = excl; g_fill[i] = excl; }
}
__global__ void k_fill(const int* __restrict__ ei) {
    int e = blockIdx.x * blockDim.x + threadIdx.x;
    if (e >= NE) return;
    int s = ei[e], d = ei[NE + e];
    int p = atomicAdd(&g_fill[d], 1);
    g_csrc[p] = s;
    g_eorig[p] = e;
}

// ================= GEMM1 fused (x@W1 -> g_h1lin, + es1/ed1), scalar FMA =================
// BM=128 BN=128 BK=16 TM=8 TN=8, 256 threads
__global__ __launch_bounds__(256) void gemm1_fused(const float* __restrict__ A,
        const float* __restrict__ B, const float* __restrict__ asrc,
        const float* __restrict__ adst) {
    __shared__ float As[16][128];
    __shared__ float Bs[16][128];
    const int tid = threadIdx.x;
    const int bm = blockIdx.y * 128, bn = blockIdx.x * 128;
    const int tcol = tid & 15, trow = tid >> 4;

    float acc[8][8];
    #pragma unroll
    for (int i = 0; i < 8; i++)
        #pragma unroll
        for (int j = 0; j < 8; j++) acc[i][j] = 0.f;

    for (int k0 = 0; k0 < FIN; k0 += 16) {
        #pragma unroll
        for (int i = tid; i < 512; i += 256) {
            int r = i >> 2, kc = (i & 3) * 4;
            float4 v = make_float4(0.f, 0.f, 0.f, 0.f);
            if (bm + r < NN) v = *(const float4*)&A[(size_t)(bm + r) * FIN + k0 + kc];
            As[kc + 0][r] = v.x; As[kc + 1][r] = v.y;
            As[kc + 2][r] = v.z; As[kc + 3][r] = v.w;
        }
        #pragma unroll
        for (int i = tid; i < 512; i += 256) {
            int kr = i >> 5, nc = (i & 31) * 4;
            *(float4*)&Bs[kr][nc] = *(const float4*)&B[(size_t)(k0 + kr) * C1 + bn + nc];
        }
        __syncthreads();
        #pragma unroll
        for (int kk = 0; kk < 16; kk++) {
            float a[8], b[8];
            #pragma unroll
            for (int i = 0; i < 8; i += 4)
                *(float4*)&a[i] = *(const float4*)&As[kk][trow * 8 + i];
            #pragma unroll
            for (int j = 0; j < 8; j += 4)
                *(float4*)&b[j] = *(const float4*)&Bs[kk][tcol * 8 + j];
            #pragma unroll
            for (int i = 0; i < 8; i++)
                #pragma unroll
                for (int j = 0; j < 8; j++) acc[i][j] += a[i] * b[j];
        }
        __syncthreads();
    }
    // store + fused attention-score epilogue
    const int headg = (bn + tcol * 8) >> 6;
    float as_[8], ad_[8];
    #pragma unroll
    for (int j = 0; j < 8; j++) {
        int col = (bn + tcol * 8 + j) & 63;
        as_[j] = asrc[headg * 64 + col];
        ad_[j] = adst[headg * 64 + col];
    }
    #pragma unroll
    for (int i = 0; i < 8; i++) {
        int r = bm + trow * 8 + i;
        bool ok = r < NN;
        if (ok) {
            float* cp = &g_h1lin[(size_t)r * C1 + bn + tcol * 8];
            *(float4*)cp       = make_float4(acc[i][0], acc[i][1], acc[i][2], acc[i][3]);
            *(float4*)(cp + 4) = make_float4(acc[i][4], acc[i][5], acc[i][6], acc[i][7]);
        }
        float es = 0.f, ed = 0.f;
        #pragma unroll
        for (int j = 0; j < 8; j++) { es += acc[i][j] * as_[j]; ed += acc[i][j] * ad_[j]; }
        es += __shfl_xor_sync(0xffffffffu, es, 1);
        es += __shfl_xor_sync(0xffffffffu, es, 2);
        es += __shfl_xor_sync(0xffffffffu, es, 4);
        ed += __shfl_xor_sync(0xffffffffu, ed, 1);
        ed += __shfl_xor_sync(0xffffffffu, ed, 2);
        ed += __shfl_xor_sync(0xffffffffu, ed, 4);
        if (ok && (tid & 7) == 0) { g_es1[r * 4 + headg] = es; g_ed1[r * 4 + headg] = ed; }
    }
}

// ================= GEMM2 fused (g_out1@W2 -> g_h2lin, + es2/ed2), scalar FMA =================
// BM=128 BN=64 BK=16 TM=8 TN=4, 256 threads
__global__ __launch_bounds__(256) void gemm2_fused(const float* __restrict__ B,
        const float* __restrict__ asrc, const float* __restrict__ adst) {
    __shared__ float As[16][128];
    __shared__ float Bs[16][64];
    const int tid = threadIdx.x;
    const int bm = blockIdx.y * 128;
    const int tcol = tid & 15, trow = tid >> 4;

    float acc[8][4];
    #pragma unroll
    for (int i = 0; i < 8; i++)
        #pragma unroll
        for (int j = 0; j < 4; j++) acc[i][j] = 0.f;

    for (int k0 = 0; k0 < C1; k0 += 16) {
        #pragma unroll
        for (int i = tid; i < 512; i += 256) {
            int r = i >> 2, kc = (i & 3) * 4;
            float4 v = make_float4(0.f, 0.f, 0.f, 0.f);
            if (bm + r < NN) v = *(const float4*)&g_out1[(size_t)(bm + r) * C1 + k0 + kc];
            As[kc + 0][r] = v.x; As[kc + 1][r] = v.y;
            As[kc + 2][r] = v.z; As[kc + 3][r] = v.w;
        }
        {
            int kr = tid >> 4, nc = (tid & 15) * 4;
            *(float4*)&Bs[kr][nc] = *(const float4*)&B[(size_t)(k0 + kr) * HID + nc];
        }
        __syncthreads();
        #pragma unroll
        for (int kk = 0; kk < 16; kk++) {
            float a[8], b[4];
            #pragma unroll
            for (int i = 0; i < 8; i += 4)
                *(float4*)&a[i] = *(const float4*)&As[kk][trow * 8 + i];
            *(float4*)&b[0] = *(const float4*)&Bs[kk][tcol * 4];
            #pragma unroll
            for (int i = 0; i < 8; i++)
                #pragma unroll
                for (int j = 0; j < 4; j++) acc[i][j] += a[i] * b[j];
        }
        __syncthreads();
    }
    float as_[4], ad_[4];
    #pragma unroll
    for (int j = 0; j < 4; j++) { as_[j] = asrc[tcol * 4 + j]; ad_[j] = adst[tcol * 4 + j]; }
    #pragma unroll
    for (int i = 0; i < 8; i++) {
        int r = bm + trow * 8 + i;
        bool ok = r < NN;
        if (ok)
            *(float4*)&g_h2lin[(size_t)r * HID + tcol * 4] =
                make_float4(acc[i][0], acc[i][1], acc[i][2], acc[i][3]);
        float es = 0.f, ed = 0.f;
        #pragma unroll
        for (int j = 0; j < 4; j++) { es += acc[i][j] * as_[j]; ed += acc[i][j] * ad_[j]; }
        #pragma unroll
        for (int o = 1; o < 16; o <<= 1) {
            es += __shfl_xor_sync(0xffffffffu, es, o);
            ed += __shfl_xor_sync(0xffffffffu, ed, o);
        }
        if (ok && (tid & 15) == 0) { g_es2[r] = es; g_ed2[r] = ed; }
    }
}

// ================= layer-1 aggregation + bias + ELU + LN (one block per dst) =================
__global__ __launch_bounds__(256) void agg1(const float* __restrict__ b1,
        const float* __restrict__ lng, const float* __restrict__ lnb) {
    __shared__ int   ssrc[64];
    __shared__ float sex[256];
    __shared__ float sden[4];
    __shared__ float sself[4];
    __shared__ float sred[16];
    __shared__ float sstat[2];
    const int d = blockIdx.x, t = threadIdx.x;
    const int r0 = g_rowstart[d], r1 = g_rowstart[d + 1];
    const int hd = t >> 6;
    const int hh = t & 3, q = t >> 2;
    const float edd = g_ed1[d * 4 + hh];
    if (t < 4) sden[t] = 0.f;
    __syncthreads();
    float acc = 0.f;
    for (int base = r0; base < r1; base += 64) {
        int cnt = min(64, r1 - base);
        float ex = 0.f;
        if (q < cnt) {
            int s = g_csrc[base + q];
            if (hh == 0) ssrc[q] = s;
            ex = expf(lrelu02(g_es1[s * 4 + hh] + edd));
        }
        sex[t] = ex;
        float ww = ex;
        ww += __shfl_xor_sync(0xffffffffu, ww, 4);
        ww += __shfl_xor_sync(0xffffffffu, ww, 8);
        ww += __shfl_xor_sync(0xffffffffu, ww, 16);
        if ((t & 31) < 4) atomicAdd(&sden[hh], ww);
        __syncthreads();
        #pragma unroll 4
        for (int q2 = 0; q2 < cnt; q2++)
            acc += g_h1lin[(size_t)ssrc[q2] * C1 + t] * sex[q2 * 4 + hd];
        __syncthreads();
    }
    if (t < 4) {
        float ex = expf(lrelu02(g_es1[d * 4 + t] + g_ed1[d * 4 + t]));
        sself[t] = ex;
        atomicAdd(&sden[t], ex);
    }
    __syncthreads();
    float rd = 1.f / (sden[hd] + 1e-16f);
    float v = (acc + sself[hd] * g_h1lin[(size_t)d * C1 + t]) * rd + b1[t];
    v = v > 0.f ? v : expm1f(v);
    float s1 = warp_sum(v), s2 = warp_sum(v * v);
    int wi = t >> 5, l = t & 31;
    if (!l) { sred[wi] = s1; sred[8 + wi] = s2; }
    __syncthreads();
    if (t == 0) {
        float S = 0.f, Q = 0.f;
        #pragma unroll
        for (int k = 0; k < 8; k++) { S += sred[k]; Q += sred[8 + k]; }
        float mu = S * (1.f / C1);
        sstat[0] = mu;
        sstat[1] = rsqrtf(Q * (1.f / C1) - mu * mu + 1e-5f);
    }
    __syncthreads();
    g_out1[(size_t)d * C1 + t] = (v - sstat[0]) * sstat[1] * lng[t] + lnb[t];
}

// ================= layer-2 aggregation + alpha + bias + LN =================
__global__ __launch_bounds__(256) void agg2(const float* __restrict__ b2,
        const float* __restrict__ lng, const float* __restrict__ lnb,
        float* __restrict__ h2out, float* __restrict__ alpha_out) {
    __shared__ int   ssrc[256];
    __shared__ float sex[256];
    __shared__ float sden[1];
    __shared__ float sselfv[1];
    __shared__ float sacc[256];
    __shared__ float sred[4];
    __shared__ float sstat[2];
    const int d = blockIdx.x, t = threadIdx.x;
    const int r0 = g_rowstart[d], r1 = g_rowstart[d + 1];
    const float edd = g_ed2[d];
    if (t == 0) sden[0] = 0.f;
    __syncthreads();
    const int c = t & 63, sub = t >> 6;
    float acc = 0.f;
    int lastbase = r0;
    for (int base = r0; base < r1; base += 256) {
        lastbase = base;
        int cnt = min(256, r1 - base);
        float ex = 0.f;
        if (t < cnt) {
            int s = g_csrc[base + t];
            ssrc[t] = s;
            ex = expf(lrelu02(g_es2[s] + edd));
        }
        sex[t] = ex;
        float ww = warp_sum(ex);
        if ((t & 31) == 0) atomicAdd(&sden[0], ww);
        __syncthreads();
        for (int qq = sub; qq < cnt; qq += 4)
            acc += g_h2lin[(size_t)ssrc[qq] * HID + c] * sex[qq];
        __syncthreads();
    }
    if (t == 0) {
        float ex = expf(lrelu02(g_es2[d] + edd));
        sselfv[0] = ex;
        atomicAdd(&sden[0], ex);
    }
    __syncthreads();
    float rd = 1.f / (sden[0] + 1e-16f);
    if (t == 0) alpha_out[NE + d] = sselfv[0] * rd;
    for (int p = r0 + t; p < r1; p += 256) {
        float exv = (p >= lastbase) ? sex[p - lastbase]
                                    : expf(lrelu02(g_es2[g_csrc[p]] + edd));
        alpha_out[g_eorig[p]] = exv * rd;
    }
    sacc[t] = acc;
    __syncthreads();
    float v = 0.f;
    if (t < 64) {
        float tot = sacc[t] + sacc[64 + t] + sacc[128 + t] + sacc[192 + t]
                  + sselfv[0] * g_h2lin[(size_t)d * HID + t];
        v = tot * rd + b2[t];
    }
    float s1 = warp_sum(t < 64 ? v : 0.f);
    float s2 = warp_sum(t < 64 ? v * v : 0.f);
    if (t < 64 && !(t & 31)) { sred[t >> 5] = s1; sred[2 + (t >> 5)] = s2; }
    __syncthreads();
    if (t == 0) {
        float S = sred[0] + sred[1], Q = sred[2] + sred[3];
        float mu = S * (1.f / HID);
        sstat[0] = mu;
        sstat[1] = rsqrtf(Q * (1.f / HID) - mu * mu + 1e-5f);
    }
    __syncthreads();
    if (t < 64)
        h2out[(size_t)d * HID + t] = (v - sstat[0]) * sstat[1] * lng[t] + lnb[t];
}

// ================= sentence/step path =================
__global__ void sent_kernel(const float* __restrict__ semb, const int* __restrict__ stepp,
                            const float* __restrict__ fc0w, const float* __restrict__ fc0b,
                            const float* __restrict__ fc1w, const float* __restrict__ fc1b,
                            const float* __restrict__ fc2w, const float* __restrict__ fc2b,
                            const float* __restrict__ lng, const float* __restrict__ lnb) {
    __shared__ float sh[64];
    __shared__ float st[2];
    int c = threadIdx.x;
    float sval = (float)(stepp[0] + 1) * 0.01f;

    float t = fmaxf(sval * fc0w[c] + fc0b[c], 0.f);
    sh[c] = t; __syncthreads();
    if (c == 0) {
        float S = 0, Q = 0;
        for (int k = 0; k < 64; k++) { S += sh[k]; Q += sh[k] * sh[k]; }
        float mu = S / 64.f; st[0] = mu; st[1] = rsqrtf(Q / 64.f - mu * mu + 1e-5f);
    }
    __syncthreads();
    float steps_c = (t - st[0]) * st[1] * lng[c] + lnb[c];
    __syncthreads();

    float u = fc1b[c];
    for (int k = 0; k < SENTD; k++) u += semb[k] * fc1w[k * 64 + c];
    u = fmaxf(u, 0.f);
    sh[c] = u; __syncthreads();
    if (c == 0) {
        float S = 0, Q = 0;
        for (int k = 0; k < 64; k++) { S += sh[k]; Q += sh[k] * sh[k]; }
        float mu = S / 64.f; st[0] = mu; st[1] = rsqrtf(Q / 64.f - mu * mu + 1e-5f);
    }
    __syncthreads();
    float sc = (u - st[0]) * st[1] * lng[c] + lnb[c] + steps_c;
    __syncthreads();
    sh[c] = sc; __syncthreads();

    float v = fc2b[c];
    for (int k = 0; k < 64; k++) v += sh[k] * fc2w[k * 64 + c];
    v = fmaxf(v, 0.f);
    __syncthreads();
    sh[c] = v; __syncthreads();
    if (c == 0) {
        float S = 0, Q = 0;
        for (int k = 0; k < 64; k++) { S += sh[k]; Q += sh[k] * sh[k]; }
        float mu = S / 64.f; st[0] = mu; st[1] = rsqrtf(Q / 64.f - mu * mu + 1e-5f);
    }
    __syncthreads();
    g_sent[c] = (v - st[0]) * st[1] * lng[c] + lnb[c];
}

// ================= dueling head =================
__global__ void head_kernel(const float* __restrict__ h2base, const int* __restrict__ activep,
                            const float* __restrict__ fc3w, const float* __restrict__ fc3b,
                            const float* __restrict__ valw, const float* __restrict__ valb,
                            const float* __restrict__ advw, const float* __restrict__ advb,
                            const float* __restrict__ lnfg, const float* __restrict__ lnfb,
                            const float* __restrict__ lnhg, const float* __restrict__ lnhb,
                            float* __restrict__ outlogits) {
    __shared__ float sh[128];
    __shared__ float sh2[64];
    __shared__ float st[3];
    int c = threadIdx.x;
    int act = activep[0];
    float a = (c < 64) ? h2base[(size_t)act * 64 + c] : g_sent[c - 64];
    sh[c] = a; __syncthreads();
    if (c == 0) {
        float S = 0, Q = 0;
        for (int k = 0; k < 128; k++) { S += sh[k]; Q += sh[k] * sh[k]; }
        float mu = S / 128.f; st[0] = mu; st[1] = rsqrtf(Q / 128.f - mu * mu + 1e-5f);
    }
    __syncthreads();
    float anf = (a - st[0]) * st[1] * lnfg[c] + lnfb[c];
    __syncthreads();
    sh[c] = anf; __syncthreads();

    float t = 0.f;
    if (c < 64) {
        t = fc3b[c];
        for (int k = 0; k < 128; k++) t += sh[k] * fc3w[k * 64 + c];
        t = fmaxf(t, 0.f);
        sh2[c] = t;
    }
    __syncthreads();
    if (c == 0) {
        float S = 0, Q = 0;
        for (int k = 0; k < 64; k++) { S += sh2[k]; Q += sh2[k] * sh2[k]; }
        float mu = S / 64.f; st[0] = mu; st[1] = rsqrtf(Q / 64.f - mu * mu + 1e-5f);
    }
    __syncthreads();
    if (c < 64) sh2[c] = (t - st[0]) * st[1] * lnhg[c] + lnhb[c];
    __syncthreads();
    if (c == 0) {
        float v = valb[0];
        for (int k = 0; k < 64; k++) v += sh2[k] * valw[k];
        st[2] = v;
    }
    __syncthreads();
    float advv = 0.f;
    if (c < 32) {
        advv = advb[c];
        for (int k = 0; k < 64; k++) advv += sh2[k] * advw[k * 32 + c];
        sh[c] = advv;
    }
    __syncthreads();
    if (c == 0) {
        float m = 0;
        for (int k = 0; k < 32; k++) m += sh[k];
        st[0] = m / 32.f;
    }
    __syncthreads();
    if (c < 32) outlogits[c] = tanhf(st[2] + advv - st[0]);
}

// ================= launch =================
extern "C" void kernel_launch(void* const* d_in, const int* in_sizes, int n_in,
                              void* d_out, int out_size) {
    const float* x      = (const float*)d_in[0];
    const int*   ei     = (const int*)d_in[1];
    const float* semb   = (const float*)d_in[2];
    const int*   active = (const int*)d_in[3];
    const int*   step   = (const int*)d_in[4];
    const float* W1     = (const float*)d_in[5];
    const float* asrc1  = (const float*)d_in[6];
    const float* adst1  = (const float*)d_in[7];
    const float* b1     = (const float*)d_in[8];
    const float* W2     = (const float*)d_in[9];
    const float* asrc2  = (const float*)d_in[10];
    const float* adst2  = (const float*)d_in[11];
    const float* b2     = (const float*)d_in[12];
    const float* fc0w   = (const float*)d_in[13];
    const float* fc0b   = (const float*)d_in[14];
    const float* fc1w   = (const float*)d_in[15];
    const float* fc1b   = (const float*)d_in[16];
    const float* fc2w   = (const float*)d_in[17];
    const float* fc2b   = (const float*)d_in[18];
    const float* fc3w   = (const float*)d_in[19];
    const float* fc3b   = (const float*)d_in[20];
    const float* valw   = (const float*)d_in[21];
    const float* valb   = (const float*)d_in[22];
    const float* advw   = (const float*)d_in[23];
    const float* advb   = (const float*)d_in[24];
    const float* lnhg   = (const float*)d_in[25];
    const float* lnhb   = (const float*)d_in[26];
    const float* lnfg   = (const float*)d_in[27];
    const float* lnfb   = (const float*)d_in[28];
    const float* lnag   = (const float*)d_in[29];
    const float* lnab   = (const float*)d_in[30];
    float* out = (float*)d_out;

    float* h2out     = out + 32;
    float* alpha_out = out + 32 + (size_t)NN * HID;

    // order chosen so launch index 3 (the one ncu profiles) is gemm1_fused
    k_zero<<<NB, 256>>>();                               // 0
    sent_kernel<<<1, 64>>>(semb, step, fc0w, fc0b, fc1w, fc1b,
                           fc2w, fc2b, lnhg, lnhb);      // 1
    k_hist<<<(NE + 255) / 256, 256>>>(ei);               // 2
    gemm1_fused<<<dim3(2, (NN + 127) / 128), 256>>>(x, W1, asrc1, adst1);  // 3 <- profiled
    k_scan1<<<NB, 256>>>();                              // 4
    k_scan2<<<1, 256>>>();                               // 5
    k_scan3<<<NB, 256>>>();                              // 6
    k_fill<<<(NE + 255) / 256, 256>>>(ei);               // 7

    agg1<<<NN, 256>>>(b1, lnag, lnab);                   // 8
    gemm2_fused<<<dim3(1, (NN + 127) / 128), 256>>>(W2, asrc2, adst2);     // 9
    agg2<<<NN, 256>>>(b2, lnhg, lnhb, h2out, alpha_out); // 10
    head_kernel<<<1, 128>>>(h2out, active, fc3w, fc3b, valw, valb, advw, advb,
                            lnfg, lnfb, lnhg, lnhb, out); // 11
}

// round 5
// speedup vs baseline: 2.0430x; 1.8692x over previous
#include <cuda_runtime.h>
#include <math.h>
#include <stdint.h>

#define NN 50000
#define NE 600000
#define FIN 128
#define HID 64
#define C1 256
#define SENTD 768

// ---------------- device scratch ----------------
__device__ __align__(16) float g_h1lin[(size_t)NN * C1];   // x@W1
__device__ __align__(16) float g_out1 [(size_t)NN * C1];   // LN(elu(agg1+b1))
__device__ __align__(16) float g_h2lin[(size_t)NN * HID];  // h1n@W2
__device__ __align__(16) float g_es1[NN * 4];
__device__ __align__(16) float g_ed1[NN * 4];
__device__ float g_es2[NN], g_ed2[NN];
__device__ float g_sent[HID];
// CSR (g_deg zero-initialized at load; re-zeroed by agg1 each call)
__device__ int g_deg[NN];
__device__ int g_rowstart[NN + 1];
__device__ int g_fill[NN];
__device__ int g_csrc[NE];
__device__ int g_eorig[NE];

// ---------------- helpers ----------------
__device__ __forceinline__ float warp_sum(float v) {
    #pragma unroll
    for (int o = 16; o; o >>= 1) v += __shfl_xor_sync(0xffffffffu, v, o);
    return v;
}
__device__ __forceinline__ float lrelu02(float v) { return v > 0.f ? v : 0.2f * v; }

__device__ __forceinline__ void cp_async16(void* smem, const void* gmem) {
    unsigned s = (unsigned)__cvta_generic_to_shared(smem);
    asm volatile("cp.async.cg.shared.global [%0], [%1], 16;\n" :: "r"(s), "l"(gmem));
}
__device__ __forceinline__ void cp_commit() { asm volatile("cp.async.commit_group;\n"); }
__device__ __forceinline__ void cp_wait0()  { asm volatile("cp.async.wait_group 0;\n"); }

// ================= CSR build =================
__global__ void k_hist(const int* __restrict__ ei) {
    int e4 = blockIdx.x * blockDim.x + threadIdx.x;
    if (e4 >= NE / 4) return;
    int4 d = ((const int4*)(ei + NE))[e4];
    atomicAdd(&g_deg[d.x], 1);
    atomicAdd(&g_deg[d.y], 1);
    atomicAdd(&g_deg[d.z], 1);
    atomicAdd(&g_deg[d.w], 1);
}

// single-block scan: 1024 threads, 13 chunks of 4096 ints
__global__ void k_scan() {
    __shared__ int wsum[32];
    __shared__ int stot;
    const int t = threadIdx.x, lane = t & 31, w = t >> 5;
    int base = 0;
    for (int c = 0; c < 13; c++) {
        int i4 = c * 1024 + t;
        int4 v = (i4 < NN / 4) ? ((const int4*)g_deg)[i4] : make_int4(0, 0, 0, 0);
        int tot = v.x + v.y + v.z + v.w;
        int inc = tot;
        #pragma unroll
        for (int o = 1; o < 32; o <<= 1) {
            int x = __shfl_up_sync(0xffffffffu, inc, o);
            if (lane >= o) inc += x;
        }
        if (lane == 31) wsum[w] = inc;
        __syncthreads();
        if (w == 0) {
            int x = wsum[lane];
            int incw = x;
            #pragma unroll
            for (int o = 1; o < 32; o <<= 1) {
                int y = __shfl_up_sync(0xffffffffu, incw, o);
                if (lane >= o) incw += y;
            }
            wsum[lane] = incw;
            if (lane == 31) stot = incw;
        }
        __syncthreads();
        int excl = base + (w ? wsum[w - 1] : 0) + inc - tot;
        if (i4 < NN / 4) {
            int idx = i4 * 4;
            int e0 = excl, e1 = e0 + v.x, e2 = e1 + v.y, e3 = e2 + v.z;
            g_rowstart[idx] = e0; g_rowstart[idx + 1] = e1;
            g_rowstart[idx + 2] = e2; g_rowstart[idx + 3] = e3;
            g_fill[idx] = e0; g_fill[idx + 1] = e1;
            g_fill[idx + 2] = e2; g_fill[idx + 3] = e3;
        }
        base += stot;
        __syncthreads();
    }
    if (t == 0) g_rowstart[NN] = NE;
}

__global__ void k_fill(const int* __restrict__ ei) {
    int e4 = blockIdx.x * blockDim.x + threadIdx.x;
    if (e4 >= NE / 4) return;
    int4 s4 = ((const int4*)ei)[e4];
    int4 d4 = ((const int4*)(ei + NE))[e4];
    int e = e4 * 4;
    int p;
    p = atomicAdd(&g_fill[d4.x], 1); g_csrc[p] = s4.x; g_eorig[p] = e;
    p = atomicAdd(&g_fill[d4.y], 1); g_csrc[p] = s4.y; g_eorig[p] = e + 1;
    p = atomicAdd(&g_fill[d4.z], 1); g_csrc[p] = s4.z; g_eorig[p] = e + 2;
    p = atomicAdd(&g_fill[d4.w], 1); g_csrc[p] = s4.w; g_eorig[p] = e + 3;
}

// ================= GEMM1 fused, cp.async double-buffered =================
// BM=128 BN=128 BK=16 TM=8 TN=8, 256 threads
__global__ __launch_bounds__(256) void gemm1_fused(const float* __restrict__ A,
        const float* __restrict__ B, const float* __restrict__ asrc,
        const float* __restrict__ adst) {
    __shared__ float As[2][16][128];
    __shared__ float Bs[2][16][128];
    const int tid = threadIdx.x;
    const int bm = blockIdx.y * 128, bn = blockIdx.x * 128;
    const int tcol = tid & 15, trow = tid >> 4;

    float acc[8][8];
    #pragma unroll
    for (int i = 0; i < 8; i++)
        #pragma unroll
        for (int j = 0; j < 8; j++) acc[i][j] = 0.f;

    float4 ra[2];
    // prologue: B(k0=0) via cp.async into stage 0; A(k0=0) into regs
    #pragma unroll
    for (int u = 0; u < 2; u++) {
        int i = tid + u * 256, kr = i >> 5, nc = (i & 31) * 4;
        cp_async16(&Bs[0][kr][nc], &B[(size_t)kr * C1 + bn + nc]);
    }
    cp_commit();
    #pragma unroll
    for (int u = 0; u < 2; u++) {
        int i = tid + u * 256, r = i >> 2, kc = (i & 3) * 4;
        ra[u] = (bm + r < NN) ? *(const float4*)&A[(size_t)(bm + r) * FIN + kc]
                              : make_float4(0.f, 0.f, 0.f, 0.f);
    }

    for (int k0 = 0; k0 < FIN; k0 += 16) {
        const int st = (k0 >> 4) & 1;
        // store A regs (transposed) into As[st]
        #pragma unroll
        for (int u = 0; u < 2; u++) {
            int i = tid + u * 256, r = i >> 2, kc = (i & 3) * 4;
            As[st][kc + 0][r] = ra[u].x; As[st][kc + 1][r] = ra[u].y;
            As[st][kc + 2][r] = ra[u].z; As[st][kc + 3][r] = ra[u].w;
        }
        cp_wait0();
        __syncthreads();
        if (k0 + 16 < FIN) {
            #pragma unroll
            for (int u = 0; u < 2; u++) {
                int i = tid + u * 256, kr = i >> 5, nc = (i & 31) * 4;
                cp_async16(&Bs[st ^ 1][kr][nc], &B[(size_t)(k0 + 16 + kr) * C1 + bn + nc]);
            }
            cp_commit();
            #pragma unroll
            for (int u = 0; u < 2; u++) {
                int i = tid + u * 256, r = i >> 2, kc = (i & 3) * 4;
                ra[u] = (bm + r < NN)
                    ? *(const float4*)&A[(size_t)(bm + r) * FIN + k0 + 16 + kc]
                    : make_float4(0.f, 0.f, 0.f, 0.f);
            }
        }
        #pragma unroll
        for (int kk = 0; kk < 16; kk++) {
            float a[8], b[8];
            #pragma unroll
            for (int i = 0; i < 8; i += 4)
                *(float4*)&a[i] = *(const float4*)&As[st][kk][trow * 8 + i];
            #pragma unroll
            for (int j = 0; j < 8; j += 4)
                *(float4*)&b[j] = *(const float4*)&Bs[st][kk][tcol * 8 + j];
            #pragma unroll
            for (int i = 0; i < 8; i++)
                #pragma unroll
                for (int j = 0; j < 8; j++) acc[i][j] += a[i] * b[j];
        }
    }
    // store + fused attention-score epilogue
    const int headg = (bn + tcol * 8) >> 6;
    float as_[8], ad_[8];
    #pragma unroll
    for (int j = 0; j < 8; j++) {
        int col = (bn + tcol * 8 + j) & 63;
        as_[j] = asrc[headg * 64 + col];
        ad_[j] = adst[headg * 64 + col];
    }
    #pragma unroll
    for (int i = 0; i < 8; i++) {
        int r = bm + trow * 8 + i;
        bool ok = r < NN;
        if (ok) {
            float* cp = &g_h1lin[(size_t)r * C1 + bn + tcol * 8];
            *(float4*)cp       = make_float4(acc[i][0], acc[i][1], acc[i][2], acc[i][3]);
            *(float4*)(cp + 4) = make_float4(acc[i][4], acc[i][5], acc[i][6], acc[i][7]);
        }
        float es = 0.f, ed = 0.f;
        #pragma unroll
        for (int j = 0; j < 8; j++) { es += acc[i][j] * as_[j]; ed += acc[i][j] * ad_[j]; }
        es += __shfl_xor_sync(0xffffffffu, es, 1);
        es += __shfl_xor_sync(0xffffffffu, es, 2);
        es += __shfl_xor_sync(0xffffffffu, es, 4);
        ed += __shfl_xor_sync(0xffffffffu, ed, 1);
        ed += __shfl_xor_sync(0xffffffffu, ed, 2);
        ed += __shfl_xor_sync(0xffffffffu, ed, 4);
        if (ok && (tid & 7) == 0) { g_es1[r * 4 + headg] = es; g_ed1[r * 4 + headg] = ed; }
    }
}

// ================= GEMM2 fused, cp.async double-buffered =================
// BM=128 BN=64 BK=16 TM=8 TN=4, 256 threads
__global__ __launch_bounds__(256) void gemm2_fused(const float* __restrict__ B,
        const float* __restrict__ asrc, const float* __restrict__ adst) {
    __shared__ float As[2][16][128];
    __shared__ float Bs[2][16][64];
    const int tid = threadIdx.x;
    const int bm = blockIdx.y * 128;
    const int tcol = tid & 15, trow = tid >> 4;

    float acc[8][4];
    #pragma unroll
    for (int i = 0; i < 8; i++)
        #pragma unroll
        for (int j = 0; j < 4; j++) acc[i][j] = 0.f;

    float4 ra[2];
    {
        int kr = tid >> 4, nc = (tid & 15) * 4;
        cp_async16(&Bs[0][kr][nc], &B[(size_t)kr * HID + nc]);
    }
    cp_commit();
    #pragma unroll
    for (int u = 0; u < 2; u++) {
        int i = tid + u * 256, r = i >> 2, kc = (i & 3) * 4;
        ra[u] = (bm + r < NN) ? *(const float4*)&g_out1[(size_t)(bm + r) * C1 + kc]
                              : make_float4(0.f, 0.f, 0.f, 0.f);
    }

    for (int k0 = 0; k0 < C1; k0 += 16) {
        const int st = (k0 >> 4) & 1;
        #pragma unroll
        for (int u = 0; u < 2; u++) {
            int i = tid + u * 256, r = i >> 2, kc = (i & 3) * 4;
            As[st][kc + 0][r] = ra[u].x; As[st][kc + 1][r] = ra[u].y;
            As[st][kc + 2][r] = ra[u].z; As[st][kc + 3][r] = ra[u].w;
        }
        cp_wait0();
        __syncthreads();
        if (k0 + 16 < C1) {
            {
                int kr = tid >> 4, nc = (tid & 15) * 4;
                cp_async16(&Bs[st ^ 1][kr][nc], &B[(size_t)(k0 + 16 + kr) * HID + nc]);
            }
            cp_commit();
            #pragma unroll
            for (int u = 0; u < 2; u++) {
                int i = tid + u * 256, r = i >> 2, kc = (i & 3) * 4;
                ra[u] = (bm + r < NN)
                    ? *(const float4*)&g_out1[(size_t)(bm + r) * C1 + k0 + 16 + kc]
                    : make_float4(0.f, 0.f, 0.f, 0.f);
            }
        }
        #pragma unroll
        for (int kk = 0; kk < 16; kk++) {
            float a[8], b[4];
            #pragma unroll
            for (int i = 0; i < 8; i += 4)
                *(float4*)&a[i] = *(const float4*)&As[st][kk][trow * 8 + i];
            *(float4*)&b[0] = *(const float4*)&Bs[st][kk][tcol * 4];
            #pragma unroll
            for (int i = 0; i < 8; i++)
                #pragma unroll
                for (int j = 0; j < 4; j++) acc[i][j] += a[i] * b[j];
        }
    }
    float as_[4], ad_[4];
    #pragma unroll
    for (int j = 0; j < 4; j++) { as_[j] = asrc[tcol * 4 + j]; ad_[j] = adst[tcol * 4 + j]; }
    #pragma unroll
    for (int i = 0; i < 8; i++) {
        int r = bm + trow * 8 + i;
        bool ok = r < NN;
        if (ok)
            *(float4*)&g_h2lin[(size_t)r * HID + tcol * 4] =
                make_float4(acc[i][0], acc[i][1], acc[i][2], acc[i][3]);
        float es = 0.f, ed = 0.f;
        #pragma unroll
        for (int j = 0; j < 4; j++) { es += acc[i][j] * as_[j]; ed += acc[i][j] * ad_[j]; }
        #pragma unroll
        for (int o = 1; o < 16; o <<= 1) {
            es += __shfl_xor_sync(0xffffffffu, es, o);
            ed += __shfl_xor_sync(0xffffffffu, ed, o);
        }
        if (ok && (tid & 15) == 0) { g_es2[r] = es; g_ed2[r] = ed; }
    }
}

// ================= layer-1 aggregation: WARP per node, syncless =================
__global__ __launch_bounds__(256) void agg1(const float* __restrict__ b1,
        const float* __restrict__ lng, const float* __restrict__ lnb) {
    const int lane = threadIdx.x & 31;
    const int d = blockIdx.x * 8 + (threadIdx.x >> 5);   // NN = 6250*8 exact
    const int r0 = g_rowstart[d], r1 = g_rowstart[d + 1];
    const int hh = lane & 3, q = lane >> 2;
    const float edd = g_ed1[d * 4 + hh];
    const float ess = g_es1[d * 4 + hh];
    const int h0 = lane >> 4;          // head of acc0 channels
    if (lane == 0) g_deg[d] = 0;       // re-zero for next call's k_hist

    float4 acc0 = make_float4(0.f, 0.f, 0.f, 0.f);
    float4 acc1 = make_float4(0.f, 0.f, 0.f, 0.f);
    float den = 0.f;
    for (int base = r0; base < r1; base += 8) {
        int cnt = min(8, r1 - base);
        int s = 0; float ex = 0.f;
        if (q < cnt) {
            s = g_csrc[base + q];
            ex = expf(lrelu02(g_es1[s * 4 + hh] + edd));
        }
        den += ex;
        for (int q2 = 0; q2 < cnt; q2++) {
            int ss   = __shfl_sync(0xffffffffu, s,  q2 * 4);
            float a0 = __shfl_sync(0xffffffffu, ex, q2 * 4 + h0);
            float a1 = __shfl_sync(0xffffffffu, ex, q2 * 4 + 2 + h0);
            const float4* hp = (const float4*)&g_h1lin[(size_t)ss * C1];
            float4 v0 = hp[lane], v1 = hp[32 + lane];
            acc0.x += v0.x * a0; acc0.y += v0.y * a0; acc0.z += v0.z * a0; acc0.w += v0.w * a0;
            acc1.x += v1.x * a1; acc1.y += v1.y * a1; acc1.z += v1.z * a1; acc1.w += v1.w * a1;
        }
    }
    // reduce den over q (bits 2..4), keep per-head
    den += __shfl_xor_sync(0xffffffffu, den, 4);
    den += __shfl_xor_sync(0xffffffffu, den, 8);
    den += __shfl_xor_sync(0xffffffffu, den, 16);
    float exs = expf(lrelu02(ess + edd));
    float rd = 1.f / (den + exs + 1e-16f);
    float rd0 = __shfl_sync(0xffffffffu, rd, h0);
    float rd1 = __shfl_sync(0xffffffffu, rd, 2 + h0);
    float ex0 = __shfl_sync(0xffffffffu, exs, h0);
    float ex1 = __shfl_sync(0xffffffffu, exs, 2 + h0);

    const float4* hp = (const float4*)&g_h1lin[(size_t)d * C1];
    float4 hs0 = hp[lane], hs1 = hp[32 + lane];
    float4 bb0 = ((const float4*)b1)[lane], bb1 = ((const float4*)b1)[32 + lane];
    float v[8];
    v[0] = (acc0.x + ex0 * hs0.x) * rd0 + bb0.x;
    v[1] = (acc0.y + ex0 * hs0.y) * rd0 + bb0.y;
    v[2] = (acc0.z + ex0 * hs0.z) * rd0 + bb0.z;
    v[3] = (acc0.w + ex0 * hs0.w) * rd0 + bb0.w;
    v[4] = (acc1.x + ex1 * hs1.x) * rd1 + bb1.x;
    v[5] = (acc1.y + ex1 * hs1.y) * rd1 + bb1.y;
    v[6] = (acc1.z + ex1 * hs1.z) * rd1 + bb1.z;
    v[7] = (acc1.w + ex1 * hs1.w) * rd1 + bb1.w;
    float s1 = 0.f, s2 = 0.f;
    #pragma unroll
    for (int i = 0; i < 8; i++) {
        v[i] = v[i] > 0.f ? v[i] : expm1f(v[i]);
        s1 += v[i]; s2 += v[i] * v[i];
    }
    s1 = warp_sum(s1); s2 = warp_sum(s2);
    float mu = s1 * (1.f / C1);
    float rs = rsqrtf(s2 * (1.f / C1) - mu * mu + 1e-5f);
    float4 g0 = ((const float4*)lng)[lane], g1 = ((const float4*)lng)[32 + lane];
    float4 q0 = ((const float4*)lnb)[lane], q1 = ((const float4*)lnb)[32 + lane];
    float4* op = (float4*)&g_out1[(size_t)d * C1];
    op[lane]      = make_float4((v[0]-mu)*rs*g0.x+q0.x, (v[1]-mu)*rs*g0.y+q0.y,
                                (v[2]-mu)*rs*g0.z+q0.z, (v[3]-mu)*rs*g0.w+q0.w);
    op[32 + lane] = make_float4((v[4]-mu)*rs*g1.x+q1.x, (v[5]-mu)*rs*g1.y+q1.y,
                                (v[6]-mu)*rs*g1.z+q1.z, (v[7]-mu)*rs*g1.w+q1.w);
}

// ================= layer-2 aggregation: WARP per node, syncless =================
__global__ __launch_bounds__(256) void agg2(const float* __restrict__ b2,
        const float* __restrict__ lng, const float* __restrict__ lnb,
        float* __restrict__ h2out, float* __restrict__ alpha_out) {
    const int lane = threadIdx.x & 31;
    const int d = blockIdx.x * 8 + (threadIdx.x >> 5);
    const int r0 = g_rowstart[d], r1 = g_rowstart[d + 1];
    const float edd = g_ed2[d];

    float2 acc = make_float2(0.f, 0.f);
    float den = 0.f;
    for (int base = r0; base < r1; base += 32) {
        int cnt = min(32, r1 - base);
        int s = 0; float ex = 0.f;
        if (lane < cnt) {
            s = g_csrc[base + lane];
            ex = expf(lrelu02(g_es2[s] + edd));
        }
        den += ex;
        for (int q2 = 0; q2 < cnt; q2++) {
            int ss  = __shfl_sync(0xffffffffu, s,  q2);
            float a = __shfl_sync(0xffffffffu, ex, q2);
            float2 v = *(const float2*)&g_h2lin[(size_t)ss * HID + lane * 2];
            acc.x += v.x * a; acc.y += v.y * a;
        }
    }
    den = warp_sum(den);
    float exs = expf(lrelu02(g_es2[d] + edd));
    float rd = 1.f / (den + exs + 1e-16f);
    if (lane == 0) alpha_out[NE + d] = exs * rd;
    // alpha for edges (recompute ex; csrc/es2 are L2-hot)
    for (int p = r0 + lane; p < r1; p += 32) {
        int sp = g_csrc[p];
        alpha_out[g_eorig[p]] = expf(lrelu02(g_es2[sp] + edd)) * rd;
    }
    float2 hs = *(const float2*)&g_h2lin[(size_t)d * HID + lane * 2];
    float2 bb = *(const float2*)&b2[lane * 2];
    float v0 = (acc.x + exs * hs.x) * rd + bb.x;
    float v1 = (acc.y + exs * hs.y) * rd + bb.y;
    float s1 = warp_sum(v0 + v1);
    float s2 = warp_sum(v0 * v0 + v1 * v1);
    float mu = s1 * (1.f / HID);
    float rs = rsqrtf(s2 * (1.f / HID) - mu * mu + 1e-5f);
    float2 gg = *(const float2*)&lng[lane * 2];
    float2 qq = *(const float2*)&lnb[lane * 2];
    *(float2*)&h2out[(size_t)d * HID + lane * 2] =
        make_float2((v0 - mu) * rs * gg.x + qq.x, (v1 - mu) * rs * gg.y + qq.y);
}

// ================= sentence/step path (1024 threads, k-split) =================
__global__ __launch_bounds__(1024) void sent_kernel(const float* __restrict__ semb,
        const int* __restrict__ stepp,
        const float* __restrict__ fc0w, const float* __restrict__ fc0b,
        const float* __restrict__ fc1w, const float* __restrict__ fc1b,
        const float* __restrict__ fc2w, const float* __restrict__ fc2b,
        const float* __restrict__ lng, const float* __restrict__ lnb) {
    __shared__ float red[16][64];
    __shared__ float sh[64];
    __shared__ float st[2];
    const int t = threadIdx.x, c = t & 63, part = t >> 6;
    const float sval = (float)(stepp[0] + 1) * 0.01f;

    // fc1 partials: 16 parts x 48 k
    {
        float u = 0.f;
        int kb = part * 48;
        #pragma unroll 8
        for (int k = 0; k < 48; k++) u += semb[kb + k] * fc1w[(kb + k) * 64 + c];
        red[part][c] = u;
    }
    // steps = LN(relu(fc0)) on threads < 64
    float steps_c = 0.f;
    {
        float tv = (t < 64) ? fmaxf(sval * fc0w[t] + fc0b[t], 0.f) : 0.f;
        float a1 = warp_sum(tv), a2 = warp_sum(tv * tv);
        if (t < 64 && (t & 31) == 0) { sh[t >> 5] = a1; sh[2 + (t >> 5)] = a2; }
        __syncthreads();
        float mu = (sh[0] + sh[1]) / 64.f;
        float rs = rsqrtf((sh[2] + sh[3]) / 64.f - mu * mu + 1e-5f);
        if (t < 64) steps_c = (tv - mu) * rs * lng[t] + lnb[t];
    }
    __syncthreads();
    // combine fc1, relu, LN, + steps
    if (t < 64) {
        float u = fc1b[t];
        #pragma unroll
        for (int p = 0; p < 16; p++) u += red[p][t];
        u = fmaxf(u, 0.f);
        float a1 = warp_sum(u), a2 = warp_sum(u * u);
        if ((t & 31) == 0) { st[t >> 5] = a1; red[15][62 + (t >> 5)] = a2; }
        __syncthreads();
        float mu = (st[0] + st[1]) / 64.f;
        float rs = rsqrtf((red[15][62] + red[15][63]) / 64.f - mu * mu + 1e-5f);
        sh[t] = (u - mu) * rs * lng[t] + lnb[t] + steps_c;
    } else { __syncthreads(); }
    __syncthreads();
    // fc2: 64x64, 4 parts x 16 k (threads < 256)
    if (t < 256) {
        float u = 0.f;
        int kb = (part & 3) * 16;
        #pragma unroll
        for (int k = 0; k < 16; k++) u += sh[kb + k] * fc2w[(kb + k) * 64 + c];
        red[part & 3][c] = u;
    }
    __syncthreads();
    if (t < 64) {
        float u = red[0][t] + red[1][t] + red[2][t] + red[3][t] + fc2b[t];
        u = fmaxf(u, 0.f);
        float a1 = warp_sum(u), a2 = warp_sum(u * u);
        if ((t & 31) == 0) { st[t >> 5] = a1; red[15][62 + (t >> 5)] = a2; }
        __syncthreads();
        float mu = (st[0] + st[1]) / 64.f;
        float rs = rsqrtf((red[15][62] + red[15][63]) / 64.f - mu * mu + 1e-5f);
        g_sent[t] = (u - mu) * rs * lng[t] + lnb[t];
    }
}

// ================= dueling head (256 threads, k-split) =================
__global__ __launch_bounds__(256) void head_kernel(const float* __restrict__ h2base,
        const int* __restrict__ activep,
        const float* __restrict__ fc3w, const float* __restrict__ fc3b,
        const float* __restrict__ valw, const float* __restrict__ valb,
        const float* __restrict__ advw, const float* __restrict__ advb,
        const float* __restrict__ lnfg, const float* __restrict__ lnfb,
        const float* __restrict__ lnhg, const float* __restrict__ lnhb,
        float* __restrict__ outlogits) {
    __shared__ float sh[128];
    __shared__ float sh2[64];
    __shared__ float red[8][64];
    __shared__ float st[8];
    const int t = threadIdx.x;
    const int act = activep[0];
    // LN over concat [h2[act], sent]
    {
        float a = 0.f;
        if (t < 128) {
            a = (t < 64) ? h2base[(size_t)act * 64 + t] : g_sent[t - 64];
        }
        float a1 = warp_sum(t < 128 ? a : 0.f), a2 = warp_sum(t < 128 ? a * a : 0.f);
        if (t < 128 && (t & 31) == 0) { st[t >> 5] = a1; st[4 + (t >> 5)] = a2; }
        __syncthreads();
        float mu = (st[0] + st[1] + st[2] + st[3]) / 128.f;
        float rs = rsqrtf((st[4] + st[5] + st[6] + st[7]) / 128.f - mu * mu + 1e-5f);
        if (t < 128) sh[t] = (a - mu) * rs * lnfg[t] + lnfb[t];
    }
    __syncthreads();
    // fc3: 128k x 64c, 4 parts x 32k
    {
        const int c = t & 63, part = t >> 6;
        float u = 0.f;
        int kb = part * 32;
        #pragma unroll 8
        for (int k = 0; k < 32; k++) u += sh[kb + k] * fc3w[(kb + k) * 64 + c];
        red[part][c] = u;
    }
    __syncthreads();
    if (t < 64) {
        float u = red[0][t] + red[1][t] + red[2][t] + red[3][t] + fc3b[t];
        u = fmaxf(u, 0.f);
        float a1 = warp_sum(u), a2 = warp_sum(u * u);
        if ((t & 31) == 0) { st[t >> 5] = a1; st[4 + (t >> 5)] = a2; }
        __syncthreads();
        float mu = (st[0] + st[1]) / 64.f;
        float rs = rsqrtf((st[4] + st[5]) / 64.f - mu * mu + 1e-5f);
        sh2[t] = (u - mu) * rs * lnhg[t] + lnhb[t];
    } else { __syncthreads(); }
    __syncthreads();
    // val (threads <64, 2-warp reduce) and adv (8 parts x 8k)
    {
        float pv = (t < 64) ? sh2[t] * valw[t] : 0.f;
        float a1 = warp_sum(pv);
        if (t < 64 && (t & 31) == 0) st[6 + (t >> 5)] = a1;
    }
    {
        const int c = t & 31, part = t >> 5;
        float u = 0.f;
        int kb = part * 8;
        #pragma unroll
        for (int k = 0; k < 8; k++) u += sh2[kb + k] * advw[(kb + k) * 32 + c];
        red[part][c] = u;
    }
    __syncthreads();
    float val = st[6] + st[7] + valb[0];
    float advv = 0.f;
    if (t < 32) {
        advv = advb[t];
        #pragma unroll
        for (int p = 0; p < 8; p++) advv += red[p][t];
    }
    float m = warp_sum(t < 32 ? advv : 0.f) * (1.f / 32.f);
    if (t < 32) outlogits[t] = tanhf(val + advv - m);
}

// ================= launch =================
extern "C" void kernel_launch(void* const* d_in, const int* in_sizes, int n_in,
                              void* d_out, int out_size) {
    const float* x      = (const float*)d_in[0];
    const int*   ei     = (const int*)d_in[1];
    const float* semb   = (const float*)d_in[2];
    const int*   active = (const int*)d_in[3];
    const int*   step   = (const int*)d_in[4];
    const float* W1     = (const float*)d_in[5];
    const float* asrc1  = (const float*)d_in[6];
    const float* adst1  = (const float*)d_in[7];
    const float* b1     = (const float*)d_in[8];
    const float* W2     = (const float*)d_in[9];
    const float* asrc2  = (const float*)d_in[10];
    const float* adst2  = (const float*)d_in[11];
    const float* b2     = (const float*)d_in[12];
    const float* fc0w   = (const float*)d_in[13];
    const float* fc0b   = (const float*)d_in[14];
    const float* fc1w   = (const float*)d_in[15];
    const float* fc1b   = (const float*)d_in[16];
    const float* fc2w   = (const float*)d_in[17];
    const float* fc2b   = (const float*)d_in[18];
    const float* fc3w   = (const float*)d_in[19];
    const float* fc3b   = (const float*)d_in[20];
    const float* valw   = (const float*)d_in[21];
    const float* valb   = (const float*)d_in[22];
    const float* advw   = (const float*)d_in[23];
    const float* advb   = (const float*)d_in[24];
    const float* lnhg   = (const float*)d_in[25];
    const float* lnhb   = (const float*)d_in[26];
    const float* lnfg   = (const float*)d_in[27];
    const float* lnfb   = (const float*)d_in[28];
    const float* lnag   = (const float*)d_in[29];
    const float* lnab   = (const float*)d_in[30];
    float* out = (float*)d_out;

    float* h2out     = out + 32;
    float* alpha_out = out + 32 + (size_t)NN * HID;

    gemm1_fused<<<dim3(2, (NN + 127) / 128), 256>>>(x, W1, asrc1, adst1);   // 0
    k_hist<<<(NE / 4 + 255) / 256, 256>>>(ei);                              // 1
    k_scan<<<1, 1024>>>();                                                  // 2
    k_fill<<<(NE / 4 + 255) / 256, 256>>>(ei);                              // 3 <- profiled
    agg1<<<NN / 8, 256>>>(b1, lnag, lnab);                                  // 4
    gemm2_fused<<<dim3(1, (NN + 127) / 128), 256>>>(W2, asrc2, adst2);      // 5
    agg2<<<NN / 8, 256>>>(b2, lnhg, lnhb, h2out, alpha_out);                // 6
    sent_kernel<<<1, 1024>>>(semb, step, fc0w, fc0b, fc1w, fc1b,
                             fc2w, fc2b, lnhg, lnhb);                       // 7
    head_kernel<<<1, 256>>>(h2out, active, fc3w, fc3b, valw, valb, advw, advb,
                            lnfg, lnfb, lnhg, lnhb, out);                   // 8
}

// round 6
// speedup vs baseline: 2.1401x; 1.0475x over previous
#include <cuda_runtime.h>
#include <cuda_fp16.h>
#include <math.h>
#include <stdint.h>

#define NN 50000
#define NE 600000
#define FIN 128
#define HID 64
#define C1 256
#define SENTD 768

// ---------------- device scratch ----------------
__device__ __align__(16) __half g_h1f16[(size_t)NN * C1];  // fp16 copy of x@W1
__device__ __align__(16) float  g_out1 [(size_t)NN * C1];  // LN(elu(agg1+b1)), GEMM2 A
__device__ __align__(16) __half g_h2f16[(size_t)NN * HID]; // fp16 copy of h1n@W2
__device__ __align__(16) float g_es1[NN * 4];
__device__ __align__(16) float g_ed1[NN * 4];
__device__ float g_es2[NN], g_ed2[NN];
__device__ float g_sent[HID];
// CSR (g_deg zero-initialized at load; re-zeroed by agg1 each call)
__device__ int g_deg[NN];
__device__ int g_rowstart[NN + 1];
__device__ int g_fill[NN];
__device__ int g_csrc[NE];
__device__ int g_eorig[NE];

// ---------------- helpers ----------------
__device__ __forceinline__ float warp_sum(float v) {
    #pragma unroll
    for (int o = 16; o; o >>= 1) v += __shfl_xor_sync(0xffffffffu, v, o);
    return v;
}
__device__ __forceinline__ float lrelu02(float v) { return v > 0.f ? v : 0.2f * v; }

__device__ __forceinline__ void cp_async16(void* smem, const void* gmem) {
    unsigned s = (unsigned)__cvta_generic_to_shared(smem);
    asm volatile("cp.async.cg.shared.global [%0], [%1], 16;\n" :: "r"(s), "l"(gmem));
}
__device__ __forceinline__ void cp_commit() { asm volatile("cp.async.commit_group;\n"); }
__device__ __forceinline__ void cp_wait0()  { asm volatile("cp.async.wait_group 0;\n"); }

// ================= CSR build =================
__global__ void k_hist(const int* __restrict__ ei) {
    int e4 = blockIdx.x * blockDim.x + threadIdx.x;
    if (e4 >= NE / 4) return;
    int4 d = ((const int4*)(ei + NE))[e4];
    atomicAdd(&g_deg[d.x], 1);
    atomicAdd(&g_deg[d.y], 1);
    atomicAdd(&g_deg[d.z], 1);
    atomicAdd(&g_deg[d.w], 1);
}

// single-block scan: 1024 threads, 13 chunks of 4096 ints
__global__ void k_scan() {
    __shared__ int wsum[32];
    __shared__ int stot;
    const int t = threadIdx.x, lane = t & 31, w = t >> 5;
    int base = 0;
    for (int c = 0; c < 13; c++) {
        int i4 = c * 1024 + t;
        int4 v = (i4 < NN / 4) ? ((const int4*)g_deg)[i4] : make_int4(0, 0, 0, 0);
        int tot = v.x + v.y + v.z + v.w;
        int inc = tot;
        #pragma unroll
        for (int o = 1; o < 32; o <<= 1) {
            int x = __shfl_up_sync(0xffffffffu, inc, o);
            if (lane >= o) inc += x;
        }
        if (lane == 31) wsum[w] = inc;
        __syncthreads();
        if (w == 0) {
            int x = wsum[lane];
            int incw = x;
            #pragma unroll
            for (int o = 1; o < 32; o <<= 1) {
                int y = __shfl_up_sync(0xffffffffu, incw, o);
                if (lane >= o) incw += y;
            }
            wsum[lane] = incw;
            if (lane == 31) stot = incw;
        }
        __syncthreads();
        int excl = base + (w ? wsum[w - 1] : 0) + inc - tot;
        if (i4 < NN / 4) {
            int idx = i4 * 4;
            int e0 = excl, e1 = e0 + v.x, e2 = e1 + v.y, e3 = e2 + v.z;
            g_rowstart[idx] = e0; g_rowstart[idx + 1] = e1;
            g_rowstart[idx + 2] = e2; g_rowstart[idx + 3] = e3;
            g_fill[idx] = e0; g_fill[idx + 1] = e1;
            g_fill[idx + 2] = e2; g_fill[idx + 3] = e3;
        }
        base += stot;
        __syncthreads();
    }
    if (t == 0) g_rowstart[NN] = NE;
}

__global__ void k_fill(const int* __restrict__ ei) {
    int e4 = blockIdx.x * blockDim.x + threadIdx.x;
    if (e4 >= NE / 4) return;
    int4 s4 = ((const int4*)ei)[e4];
    int4 d4 = ((const int4*)(ei + NE))[e4];
    int e = e4 * 4;
    int p;
    p = atomicAdd(&g_fill[d4.x], 1); g_csrc[p] = s4.x; g_eorig[p] = e;
    p = atomicAdd(&g_fill[d4.y], 1); g_csrc[p] = s4.y; g_eorig[p] = e + 1;
    p = atomicAdd(&g_fill[d4.z], 1); g_csrc[p] = s4.z; g_eorig[p] = e + 2;
    p = atomicAdd(&g_fill[d4.w], 1); g_csrc[p] = s4.w; g_eorig[p] = e + 3;
}

// ================= GEMM1 fused, cp.async double-buffered, fp16 output =================
// BM=128 BN=128 BK=16 TM=8 TN=8, 256 threads
__global__ __launch_bounds__(256) void gemm1_fused(const float* __restrict__ A,
        const float* __restrict__ B, const float* __restrict__ asrc,
        const float* __restrict__ adst) {
    __shared__ float As[2][16][128];
    __shared__ float Bs[2][16][128];
    const int tid = threadIdx.x;
    const int bm = blockIdx.y * 128, bn = blockIdx.x * 128;
    const int tcol = tid & 15, trow = tid >> 4;

    float acc[8][8];
    #pragma unroll
    for (int i = 0; i < 8; i++)
        #pragma unroll
        for (int j = 0; j < 8; j++) acc[i][j] = 0.f;

    float4 ra[2];
    #pragma unroll
    for (int u = 0; u < 2; u++) {
        int i = tid + u * 256, kr = i >> 5, nc = (i & 31) * 4;
        cp_async16(&Bs[0][kr][nc], &B[(size_t)kr * C1 + bn + nc]);
    }
    cp_commit();
    #pragma unroll
    for (int u = 0; u < 2; u++) {
        int i = tid + u * 256, r = i >> 2, kc = (i & 3) * 4;
        ra[u] = (bm + r < NN) ? *(const float4*)&A[(size_t)(bm + r) * FIN + kc]
                              : make_float4(0.f, 0.f, 0.f, 0.f);
    }

    for (int k0 = 0; k0 < FIN; k0 += 16) {
        const int st = (k0 >> 4) & 1;
        #pragma unroll
        for (int u = 0; u < 2; u++) {
            int i = tid + u * 256, r = i >> 2, kc = (i & 3) * 4;
            As[st][kc + 0][r] = ra[u].x; As[st][kc + 1][r] = ra[u].y;
            As[st][kc + 2][r] = ra[u].z; As[st][kc + 3][r] = ra[u].w;
        }
        cp_wait0();
        __syncthreads();
        if (k0 + 16 < FIN) {
            #pragma unroll
            for (int u = 0; u < 2; u++) {
                int i = tid + u * 256, kr = i >> 5, nc = (i & 31) * 4;
                cp_async16(&Bs[st ^ 1][kr][nc], &B[(size_t)(k0 + 16 + kr) * C1 + bn + nc]);
            }
            cp_commit();
            #pragma unroll
            for (int u = 0; u < 2; u++) {
                int i = tid + u * 256, r = i >> 2, kc = (i & 3) * 4;
                ra[u] = (bm + r < NN)
                    ? *(const float4*)&A[(size_t)(bm + r) * FIN + k0 + 16 + kc]
                    : make_float4(0.f, 0.f, 0.f, 0.f);
            }
        }
        #pragma unroll
        for (int kk = 0; kk < 16; kk++) {
            float a[8], b[8];
            #pragma unroll
            for (int i = 0; i < 8; i += 4)
                *(float4*)&a[i] = *(const float4*)&As[st][kk][trow * 8 + i];
            #pragma unroll
            for (int j = 0; j < 8; j += 4)
                *(float4*)&b[j] = *(const float4*)&Bs[st][kk][tcol * 8 + j];
            #pragma unroll
            for (int i = 0; i < 8; i++)
                #pragma unroll
                for (int j = 0; j < 8; j++) acc[i][j] += a[i] * b[j];
        }
    }
    // fp16 store + fused attention-score epilogue
    const int headg = (bn + tcol * 8) >> 6;
    float as_[8], ad_[8];
    #pragma unroll
    for (int j = 0; j < 8; j++) {
        int col = (bn + tcol * 8 + j) & 63;
        as_[j] = asrc[headg * 64 + col];
        ad_[j] = adst[headg * 64 + col];
    }
    #pragma unroll
    for (int i = 0; i < 8; i++) {
        int r = bm + trow * 8 + i;
        bool ok = r < NN;
        if (ok) {
            __half2 h0 = __floats2half2_rn(acc[i][0], acc[i][1]);
            __half2 h1 = __floats2half2_rn(acc[i][2], acc[i][3]);
            __half2 h2 = __floats2half2_rn(acc[i][4], acc[i][5]);
            __half2 h3 = __floats2half2_rn(acc[i][6], acc[i][7]);
            uint4 pk = make_uint4(*(unsigned*)&h0, *(unsigned*)&h1,
                                  *(unsigned*)&h2, *(unsigned*)&h3);
            *(uint4*)&g_h1f16[(size_t)r * C1 + bn + tcol * 8] = pk;
        }
        float es = 0.f, ed = 0.f;
        #pragma unroll
        for (int j = 0; j < 8; j++) { es += acc[i][j] * as_[j]; ed += acc[i][j] * ad_[j]; }
        es += __shfl_xor_sync(0xffffffffu, es, 1);
        es += __shfl_xor_sync(0xffffffffu, es, 2);
        es += __shfl_xor_sync(0xffffffffu, es, 4);
        ed += __shfl_xor_sync(0xffffffffu, ed, 1);
        ed += __shfl_xor_sync(0xffffffffu, ed, 2);
        ed += __shfl_xor_sync(0xffffffffu, ed, 4);
        if (ok && (tid & 7) == 0) { g_es1[r * 4 + headg] = es; g_ed1[r * 4 + headg] = ed; }
    }
}

// ================= GEMM2 fused, cp.async double-buffered, fp16 output =================
// BM=128 BN=64 BK=16 TM=8 TN=4, 256 threads
__global__ __launch_bounds__(256) void gemm2_fused(const float* __restrict__ B,
        const float* __restrict__ asrc, const float* __restrict__ adst) {
    __shared__ float As[2][16][128];
    __shared__ float Bs[2][16][64];
    const int tid = threadIdx.x;
    const int bm = blockIdx.y * 128;
    const int tcol = tid & 15, trow = tid >> 4;

    float acc[8][4];
    #pragma unroll
    for (int i = 0; i < 8; i++)
        #pragma unroll
        for (int j = 0; j < 4; j++) acc[i][j] = 0.f;

    float4 ra[2];
    {
        int kr = tid >> 4, nc = (tid & 15) * 4;
        cp_async16(&Bs[0][kr][nc], &B[(size_t)kr * HID + nc]);
    }
    cp_commit();
    #pragma unroll
    for (int u = 0; u < 2; u++) {
        int i = tid + u * 256, r = i >> 2, kc = (i & 3) * 4;
        ra[u] = (bm + r < NN) ? *(const float4*)&g_out1[(size_t)(bm + r) * C1 + kc]
                              : make_float4(0.f, 0.f, 0.f, 0.f);
    }

    for (int k0 = 0; k0 < C1; k0 += 16) {
        const int st = (k0 >> 4) & 1;
        #pragma unroll
        for (int u = 0; u < 2; u++) {
            int i = tid + u * 256, r = i >> 2, kc = (i & 3) * 4;
            As[st][kc + 0][r] = ra[u].x; As[st][kc + 1][r] = ra[u].y;
            As[st][kc + 2][r] = ra[u].z; As[st][kc + 3][r] = ra[u].w;
        }
        cp_wait0();
        __syncthreads();
        if (k0 + 16 < C1) {
            {
                int kr = tid >> 4, nc = (tid & 15) * 4;
                cp_async16(&Bs[st ^ 1][kr][nc], &B[(size_t)(k0 + 16 + kr) * HID + nc]);
            }
            cp_commit();
            #pragma unroll
            for (int u = 0; u < 2; u++) {
                int i = tid + u * 256, r = i >> 2, kc = (i & 3) * 4;
                ra[u] = (bm + r < NN)
                    ? *(const float4*)&g_out1[(size_t)(bm + r) * C1 + k0 + 16 + kc]
                    : make_float4(0.f, 0.f, 0.f, 0.f);
            }
        }
        #pragma unroll
        for (int kk = 0; kk < 16; kk++) {
            float a[8], b[4];
            #pragma unroll
            for (int i = 0; i < 8; i += 4)
                *(float4*)&a[i] = *(const float4*)&As[st][kk][trow * 8 + i];
            *(float4*)&b[0] = *(const float4*)&Bs[st][kk][tcol * 4];
            #pragma unroll
            for (int i = 0; i < 8; i++)
                #pragma unroll
                for (int j = 0; j < 4; j++) acc[i][j] += a[i] * b[j];
        }
    }
    float as_[4], ad_[4];
    #pragma unroll
    for (int j = 0; j < 4; j++) { as_[j] = asrc[tcol * 4 + j]; ad_[j] = adst[tcol * 4 + j]; }
    #pragma unroll
    for (int i = 0; i < 8; i++) {
        int r = bm + trow * 8 + i;
        bool ok = r < NN;
        if (ok) {
            __half2 h0 = __floats2half2_rn(acc[i][0], acc[i][1]);
            __half2 h1 = __floats2half2_rn(acc[i][2], acc[i][3]);
            uint2 pk = make_uint2(*(unsigned*)&h0, *(unsigned*)&h1);
            *(uint2*)&g_h2f16[(size_t)r * HID + tcol * 4] = pk;
        }
        float es = 0.f, ed = 0.f;
        #pragma unroll
        for (int j = 0; j < 4; j++) { es += acc[i][j] * as_[j]; ed += acc[i][j] * ad_[j]; }
        #pragma unroll
        for (int o = 1; o < 16; o <<= 1) {
            es += __shfl_xor_sync(0xffffffffu, es, o);
            ed += __shfl_xor_sync(0xffffffffu, ed, o);
        }
        if (ok && (tid & 15) == 0) { g_es2[r] = es; g_ed2[r] = ed; }
    }
}

// ================= layer-1 aggregation: WARP per node, fp16 gather =================
__global__ __launch_bounds__(256) void agg1(const float* __restrict__ b1,
        const float* __restrict__ lng, const float* __restrict__ lnb) {
    const int lane = threadIdx.x & 31;
    const int d = blockIdx.x * 8 + (threadIdx.x >> 5);   // NN = 6250*8 exact
    const int r0 = g_rowstart[d], r1 = g_rowstart[d + 1];
    const int hh = lane & 3, q = lane >> 2;
    const int h = lane >> 3;           // head owning this lane's 8 channels
    const float edd = g_ed1[d * 4 + hh];
    const float ess = g_es1[d * 4 + hh];
    if (lane == 0) g_deg[d] = 0;       // re-zero for next call's k_hist

    float acc[8];
    #pragma unroll
    for (int i = 0; i < 8; i++) acc[i] = 0.f;
    float den = 0.f;
    for (int base = r0; base < r1; base += 8) {
        int cnt = min(8, r1 - base);
        int s = 0; float ex = 0.f;
        if (q < cnt) {
            s = g_csrc[base + q];
            ex = expf(lrelu02(g_es1[s * 4 + hh] + edd));
        }
        den += ex;
        for (int q2 = 0; q2 < cnt; q2++) {
            int ss  = __shfl_sync(0xffffffffu, s,  q2 * 4);
            float a = __shfl_sync(0xffffffffu, ex, q2 * 4 + h);
            uint4 pk = *(const uint4*)&g_h1f16[(size_t)ss * C1 + lane * 8];
            float2 f0 = __half22float2(*(__half2*)&pk.x);
            float2 f1 = __half22float2(*(__half2*)&pk.y);
            float2 f2 = __half22float2(*(__half2*)&pk.z);
            float2 f3 = __half22float2(*(__half2*)&pk.w);
            acc[0] += f0.x * a; acc[1] += f0.y * a;
            acc[2] += f1.x * a; acc[3] += f1.y * a;
            acc[4] += f2.x * a; acc[5] += f2.y * a;
            acc[6] += f3.x * a; acc[7] += f3.y * a;
        }
    }
    // reduce den over q (bits 2..4), keep per-head (indexed by hh)
    den += __shfl_xor_sync(0xffffffffu, den, 4);
    den += __shfl_xor_sync(0xffffffffu, den, 8);
    den += __shfl_xor_sync(0xffffffffu, den, 16);
    float exs = expf(lrelu02(ess + edd));
    float rd = 1.f / (den + exs + 1e-16f);
    float rdh = __shfl_sync(0xffffffffu, rd, h);
    float exh = __shfl_sync(0xffffffffu, exs, h);

    uint4 pks = *(const uint4*)&g_h1f16[(size_t)d * C1 + lane * 8];
    float2 s0 = __half22float2(*(__half2*)&pks.x);
    float2 s1 = __half22float2(*(__half2*)&pks.y);
    float2 s2 = __half22float2(*(__half2*)&pks.z);
    float2 s3 = __half22float2(*(__half2*)&pks.w);
    float sf[8] = { s0.x, s0.y, s1.x, s1.y, s2.x, s2.y, s3.x, s3.y };

    float4 bb0 = ((const float4*)b1)[lane * 2], bb1 = ((const float4*)b1)[lane * 2 + 1];
    float bb[8] = { bb0.x, bb0.y, bb0.z, bb0.w, bb1.x, bb1.y, bb1.z, bb1.w };
    float v[8], sum1 = 0.f, sum2 = 0.f;
    #pragma unroll
    for (int i = 0; i < 8; i++) {
        v[i] = (acc[i] + exh * sf[i]) * rdh + bb[i];
        v[i] = v[i] > 0.f ? v[i] : expm1f(v[i]);
        sum1 += v[i]; sum2 += v[i] * v[i];
    }
    sum1 = warp_sum(sum1); sum2 = warp_sum(sum2);
    float mu = sum1 * (1.f / C1);
    float rs = rsqrtf(sum2 * (1.f / C1) - mu * mu + 1e-5f);
    float4 g0 = ((const float4*)lng)[lane * 2], g1 = ((const float4*)lng)[lane * 2 + 1];
    float4 q0 = ((const float4*)lnb)[lane * 2], q1 = ((const float4*)lnb)[lane * 2 + 1];
    float gg[8] = { g0.x, g0.y, g0.z, g0.w, g1.x, g1.y, g1.z, g1.w };
    float qq[8] = { q0.x, q0.y, q0.z, q0.w, q1.x, q1.y, q1.z, q1.w };
    float o[8];
    #pragma unroll
    for (int i = 0; i < 8; i++) o[i] = (v[i] - mu) * rs * gg[i] + qq[i];
    float4* op = (float4*)&g_out1[(size_t)d * C1 + lane * 8];
    op[0] = make_float4(o[0], o[1], o[2], o[3]);
    op[1] = make_float4(o[4], o[5], o[6], o[7]);
}

// ================= layer-2 aggregation: WARP per node, fp16 gather =================
__global__ __launch_bounds__(256) void agg2(const float* __restrict__ b2,
        const float* __restrict__ lng, const float* __restrict__ lnb,
        float* __restrict__ h2out, float* __restrict__ alpha_out) {
    const int lane = threadIdx.x & 31;
    const int d = blockIdx.x * 8 + (threadIdx.x >> 5);
    const int r0 = g_rowstart[d], r1 = g_rowstart[d + 1];
    const float edd = g_ed2[d];

    float2 acc = make_float2(0.f, 0.f);
    float den = 0.f;
    for (int base = r0; base < r1; base += 32) {
        int cnt = min(32, r1 - base);
        int s = 0; float ex = 0.f;
        if (lane < cnt) {
            s = g_csrc[base + lane];
            ex = expf(lrelu02(g_es2[s] + edd));
        }
        den += ex;
        for (int q2 = 0; q2 < cnt; q2++) {
            int ss  = __shfl_sync(0xffffffffu, s,  q2);
            float a = __shfl_sync(0xffffffffu, ex, q2);
            unsigned pk = *(const unsigned*)&g_h2f16[(size_t)ss * HID + lane * 2];
            float2 v = __half22float2(*(__half2*)&pk);
            acc.x += v.x * a; acc.y += v.y * a;
        }
    }
    den = warp_sum(den);
    float exs = expf(lrelu02(g_es2[d] + edd));
    float rd = 1.f / (den + exs + 1e-16f);
    if (lane == 0) alpha_out[NE + d] = exs * rd;
    for (int p = r0 + lane; p < r1; p += 32) {
        int sp = g_csrc[p];
        alpha_out[g_eorig[p]] = expf(lrelu02(g_es2[sp] + edd)) * rd;
    }
    unsigned pks = *(const unsigned*)&g_h2f16[(size_t)d * HID + lane * 2];
    float2 hs = __half22float2(*(__half2*)&pks);
    float2 bb = *(const float2*)&b2[lane * 2];
    float v0 = (acc.x + exs * hs.x) * rd + bb.x;
    float v1 = (acc.y + exs * hs.y) * rd + bb.y;
    float s1 = warp_sum(v0 + v1);
    float s2 = warp_sum(v0 * v0 + v1 * v1);
    float mu = s1 * (1.f / HID);
    float rs = rsqrtf(s2 * (1.f / HID) - mu * mu + 1e-5f);
    float2 gg = *(const float2*)&lng[lane * 2];
    float2 qq = *(const float2*)&lnb[lane * 2];
    *(float2*)&h2out[(size_t)d * HID + lane * 2] =
        make_float2((v0 - mu) * rs * gg.x + qq.x, (v1 - mu) * rs * gg.y + qq.y);
}

// ================= sentence/step path (1024 threads, k-split) =================
__global__ __launch_bounds__(1024) void sent_kernel(const float* __restrict__ semb,
        const int* __restrict__ stepp,
        const float* __restrict__ fc0w, const float* __restrict__ fc0b,
        const float* __restrict__ fc1w, const float* __restrict__ fc1b,
        const float* __restrict__ fc2w, const float* __restrict__ fc2b,
        const float* __restrict__ lng, const float* __restrict__ lnb) {
    __shared__ float red[16][64];
    __shared__ float sh[64];
    __shared__ float st[2];
    const int t = threadIdx.x, c = t & 63, part = t >> 6;
    const float sval = (float)(stepp[0] + 1) * 0.01f;

    {
        float u = 0.f;
        int kb = part * 48;
        #pragma unroll 8
        for (int k = 0; k < 48; k++) u += semb[kb + k] * fc1w[(kb + k) * 64 + c];
        red[part][c] = u;
    }
    float steps_c = 0.f;
    {
        float tv = (t < 64) ? fmaxf(sval * fc0w[t] + fc0b[t], 0.f) : 0.f;
        float a1 = warp_sum(tv), a2 = warp_sum(tv * tv);
        if (t < 64 && (t & 31) == 0) { sh[t >> 5] = a1; sh[2 + (t >> 5)] = a2; }
        __syncthreads();
        float mu = (sh[0] + sh[1]) / 64.f;
        float rs = rsqrtf((sh[2] + sh[3]) / 64.f - mu * mu + 1e-5f);
        if (t < 64) steps_c = (tv - mu) * rs * lng[t] + lnb[t];
    }
    __syncthreads();
    if (t < 64) {
        float u = fc1b[t];
        #pragma unroll
        for (int p = 0; p < 16; p++) u += red[p][t];
        u = fmaxf(u, 0.f);
        float a1 = warp_sum(u), a2 = warp_sum(u * u);
        if ((t & 31) == 0) { st[t >> 5] = a1; red[15][62 + (t >> 5)] = a2; }
        __syncthreads();
        float mu = (st[0] + st[1]) / 64.f;
        float rs = rsqrtf((red[15][62] + red[15][63]) / 64.f - mu * mu + 1e-5f);
        sh[t] = (u - mu) * rs * lng[t] + lnb[t] + steps_c;
    } else { __syncthreads(); }
    __syncthreads();
    if (t < 256) {
        float u = 0.f;
        int kb = (part & 3) * 16;
        #pragma unroll
        for (int k = 0; k < 16; k++) u += sh[kb + k] * fc2w[(kb + k) * 64 + c];
        red[part & 3][c] = u;
    }
    __syncthreads();
    if (t < 64) {
        float u = red[0][t] + red[1][t] + red[2][t] + red[3][t] + fc2b[t];
        u = fmaxf(u, 0.f);
        float a1 = warp_sum(u), a2 = warp_sum(u * u);
        if ((t & 31) == 0) { st[t >> 5] = a1; red[15][62 + (t >> 5)] = a2; }
        __syncthreads();
        float mu = (st[0] + st[1]) / 64.f;
        float rs = rsqrtf((red[15][62] + red[15][63]) / 64.f - mu * mu + 1e-5f);
        g_sent[t] = (u - mu) * rs * lng[t] + lnb[t];
    }
}

// ================= dueling head (256 threads, k-split) =================
__global__ __launch_bounds__(256) void head_kernel(const float* __restrict__ h2base,
        const int* __restrict__ activep,
        const float* __restrict__ fc3w, const float* __restrict__ fc3b,
        const float* __restrict__ valw, const float* __restrict__ valb,
        const float* __restrict__ advw, const float* __restrict__ advb,
        const float* __restrict__ lnfg, const float* __restrict__ lnfb,
        const float* __restrict__ lnhg, const float* __restrict__ lnhb,
        float* __restrict__ outlogits) {
    __shared__ float sh[128];
    __shared__ float sh2[64];
    __shared__ float red[8][64];
    __shared__ float st[8];
    const int t = threadIdx.x;
    const int act = activep[0];
    {
        float a = 0.f;
        if (t < 128) {
            a = (t < 64) ? h2base[(size_t)act * 64 + t] : g_sent[t - 64];
        }
        float a1 = warp_sum(t < 128 ? a : 0.f), a2 = warp_sum(t < 128 ? a * a : 0.f);
        if (t < 128 && (t & 31) == 0) { st[t >> 5] = a1; st[4 + (t >> 5)] = a2; }
        __syncthreads();
        float mu = (st[0] + st[1] + st[2] + st[3]) / 128.f;
        float rs = rsqrtf((st[4] + st[5] + st[6] + st[7]) / 128.f - mu * mu + 1e-5f);
        if (t < 128) sh[t] = (a - mu) * rs * lnfg[t] + lnfb[t];
    }
    __syncthreads();
    {
        const int c = t & 63, part = t >> 6;
        float u = 0.f;
        int kb = part * 32;
        #pragma unroll 8
        for (int k = 0; k < 32; k++) u += sh[kb + k] * fc3w[(kb + k) * 64 + c];
        red[part][c] = u;
    }
    __syncthreads();
    if (t < 64) {
        float u = red[0][t] + red[1][t] + red[2][t] + red[3][t] + fc3b[t];
        u = fmaxf(u, 0.f);
        float a1 = warp_sum(u), a2 = warp_sum(u * u);
        if ((t & 31) == 0) { st[t >> 5] = a1; st[4 + (t >> 5)] = a2; }
        __syncthreads();
        float mu = (st[0] + st[1]) / 64.f;
        float rs = rsqrtf((st[4] + st[5]) / 64.f - mu * mu + 1e-5f);
        sh2[t] = (u - mu) * rs * lnhg[t] + lnhb[t];
    } else { __syncthreads(); }
    __syncthreads();
    {
        float pv = (t < 64) ? sh2[t] * valw[t] : 0.f;
        float a1 = warp_sum(pv);
        if (t < 64 && (t & 31) == 0) st[6 + (t >> 5)] = a1;
    }
    {
        const int c = t & 31, part = t >> 5;
        float u = 0.f;
        int kb = part * 8;
        #pragma unroll
        for (int k = 0; k < 8; k++) u += sh2[kb + k] * advw[(kb + k) * 32 + c];
        red[part][c] = u;
    }
    __syncthreads();
    float val = st[6] + st[7] + valb[0];
    float advv = 0.f;
    if (t < 32) {
        advv = advb[t];
        #pragma unroll
        for (int p = 0; p < 8; p++) advv += red[p][t];
    }
    float m = warp_sum(t < 32 ? advv : 0.f) * (1.f / 32.f);
    if (t < 32) outlogits[t] = tanhf(val + advv - m);
}

// ================= launch =================
extern "C" void kernel_launch(void* const* d_in, const int* in_sizes, int n_in,
                              void* d_out, int out_size) {
    const float* x      = (const float*)d_in[0];
    const int*   ei     = (const int*)d_in[1];
    const float* semb   = (const float*)d_in[2];
    const int*   active = (const int*)d_in[3];
    const int*   step   = (const int*)d_in[4];
    const float* W1     = (const float*)d_in[5];
    const float* asrc1  = (const float*)d_in[6];
    const float* adst1  = (const float*)d_in[7];
    const float* b1     = (const float*)d_in[8];
    const float* W2     = (const float*)d_in[9];
    const float* asrc2  = (const float*)d_in[10];
    const float* adst2  = (const float*)d_in[11];
    const float* b2     = (const float*)d_in[12];
    const float* fc0w   = (const float*)d_in[13];
    const float* fc0b   = (const float*)d_in[14];
    const float* fc1w   = (const float*)d_in[15];
    const float* fc1b   = (const float*)d_in[16];
    const float* fc2w   = (const float*)d_in[17];
    const float* fc2b   = (const float*)d_in[18];
    const float* fc3w   = (const float*)d_in[19];
    const float* fc3b   = (const float*)d_in[20];
    const float* valw   = (const float*)d_in[21];
    const float* valb   = (const float*)d_in[22];
    const float* advw   = (const float*)d_in[23];
    const float* advb   = (const float*)d_in[24];
    const float* lnhg   = (const float*)d_in[25];
    const float* lnhb   = (const float*)d_in[26];
    const float* lnfg   = (const float*)d_in[27];
    const float* lnfb   = (const float*)d_in[28];
    const float* lnag   = (const float*)d_in[29];
    const float* lnab   = (const float*)d_in[30];
    float* out = (float*)d_out;

    float* h2out     = out + 32;
    float* alpha_out = out + 32 + (size_t)NN * HID;

    gemm1_fused<<<dim3(2, (NN + 127) / 128), 256>>>(x, W1, asrc1, adst1);   // 0
    k_hist<<<(NE / 4 + 255) / 256, 256>>>(ei);                              // 1
    k_scan<<<1, 1024>>>();                                                  // 2
    k_fill<<<(NE / 4 + 255) / 256, 256>>>(ei);                              // 3
    agg1<<<NN / 8, 256>>>(b1, lnag, lnab);                                  // 4
    gemm2_fused<<<dim3(1, (NN + 127) / 128), 256>>>(W2, asrc2, adst2);      // 5
    agg2<<<NN / 8, 256>>>(b2, lnhg, lnhb, h2out, alpha_out);                // 6
    sent_kernel<<<1, 1024>>>(semb, step, fc0w, fc0b, fc1w, fc1b,
                             fc2w, fc2b, lnhg, lnhb);                       // 7
    head_kernel<<<1, 256>>>(h2out, active, fc3w, fc3b, valw, valb, advw, advb,
                            lnfg, lnfb, lnhg, lnhb, out);                   // 8
}